// round 1
// baseline (speedup 1.0000x reference)
#include <cuda_runtime.h>

// ---------------------------------------------------------------------------
// CrossAttention: out = softmax((x Wq)(ctx Wk)^T * scale) (ctx Wv) Wout + bout
// b=4, n=2048, m=1024, qd=1024, cd=768, heads=8, dim_head=64, inner=512
// ---------------------------------------------------------------------------

#define B_    4
#define N_    2048
#define M_    1024
#define QD_   1024
#define CD_   768
#define H_    8
#define D_    64
#define INNER_ 512
#define SCALE_ 0.125f   // 64^-0.5

// Scratch (device globals: allocation-free rule)
__device__ __align__(16) static float g_q[(size_t)B_ * N_ * INNER_];       // 16 MB
__device__ __align__(16) static float g_k[(size_t)B_ * M_ * INNER_];       //  8 MB
__device__ __align__(16) static float g_v[(size_t)B_ * M_ * INNER_];       //  8 MB
__device__ __align__(16) static float g_s[(size_t)B_ * H_ * N_ * M_];      // 256 MB
__device__ __align__(16) static float g_o[(size_t)B_ * N_ * INNER_];       // 16 MB

// ---------------------------------------------------------------------------
// Generic register-tiled SGEMM.
//   TB=false: C[M,N] = A[M,K](lda) * B[K,N](ldb)
//   TB=true : C[M,N] = A[M,K](lda) * B[N,K](ldb)^T
// Batched via grid.z: z -> (zb = z/8, zh = z%8), pointer offsets
//   base += zb*s?b + zh*s?h   (pass zeros for unbatched).
// All dims assumed to divide tile sizes exactly (true for this problem).
// ---------------------------------------------------------------------------
template <int BM, int BN, int BK, int TM, int TN, bool TB, bool BIAS>
__global__ void __launch_bounds__((BM / TM) * (BN / TN))
sgemm_k(const float* __restrict__ A, const float* __restrict__ Bp,
        float* __restrict__ C, const float* __restrict__ bias,
        int K, int lda, int ldb, int ldc,
        long sAb, long sAh, long sBb, long sBh, long sCb, long sCh)
{
    constexpr int THREADS = (BM / TM) * (BN / TN);
    const int z  = blockIdx.z;
    const int zb = z >> 3, zh = z & 7;
    A  += (long)zb * sAb + (long)zh * sAh;
    Bp += (long)zb * sBb + (long)zh * sBh;
    C  += (long)zb * sCb + (long)zh * sCh;

    __shared__ float As[BK][BM];
    __shared__ float Bs[BK][BN];

    const int tid = threadIdx.x;
    const int tx  = tid % (BN / TN);
    const int ty  = tid / (BN / TN);
    const int rowC = blockIdx.y * BM + ty * TM;
    const int colC = blockIdx.x * BN + tx * TN;

    float acc[TM][TN];
#pragma unroll
    for (int i = 0; i < TM; i++)
#pragma unroll
        for (int j = 0; j < TN; j++) acc[i][j] = 0.f;

    for (int k0 = 0; k0 < K; k0 += BK) {
        // ---- load A tile (BM x BK), store transposed As[k][m]
#pragma unroll
        for (int i = tid; i < BM * BK / 4; i += THREADS) {
            int r  = i / (BK / 4);
            int c4 = (i % (BK / 4)) * 4;
            float4 t = *reinterpret_cast<const float4*>(
                &A[(long)(blockIdx.y * BM + r) * lda + k0 + c4]);
            As[c4 + 0][r] = t.x; As[c4 + 1][r] = t.y;
            As[c4 + 2][r] = t.z; As[c4 + 3][r] = t.w;
        }
        // ---- load B tile
        if (!TB) {
#pragma unroll
            for (int i = tid; i < BK * BN / 4; i += THREADS) {
                int r  = i / (BN / 4);
                int c4 = (i % (BN / 4)) * 4;
                *reinterpret_cast<float4*>(&Bs[r][c4]) =
                    *reinterpret_cast<const float4*>(
                        &Bp[(long)(k0 + r) * ldb + blockIdx.x * BN + c4]);
            }
        } else {
#pragma unroll
            for (int i = tid; i < BN * BK / 4; i += THREADS) {
                int r  = i / (BK / 4);
                int c4 = (i % (BK / 4)) * 4;
                float4 t = *reinterpret_cast<const float4*>(
                    &Bp[(long)(blockIdx.x * BN + r) * ldb + k0 + c4]);
                Bs[c4 + 0][r] = t.x; Bs[c4 + 1][r] = t.y;
                Bs[c4 + 2][r] = t.z; Bs[c4 + 3][r] = t.w;
            }
        }
        __syncthreads();

        // ---- compute
#pragma unroll
        for (int kk = 0; kk < BK; kk++) {
            float a[TM], b[TN];
#pragma unroll
            for (int i = 0; i < TM; i += 4) {
                float4 t = *reinterpret_cast<const float4*>(&As[kk][ty * TM + i]);
                a[i] = t.x; a[i + 1] = t.y; a[i + 2] = t.z; a[i + 3] = t.w;
            }
#pragma unroll
            for (int j = 0; j < TN; j += 4) {
                float4 t = *reinterpret_cast<const float4*>(&Bs[kk][tx * TN + j]);
                b[j] = t.x; b[j + 1] = t.y; b[j + 2] = t.z; b[j + 3] = t.w;
            }
#pragma unroll
            for (int i = 0; i < TM; i++)
#pragma unroll
                for (int j = 0; j < TN; j++)
                    acc[i][j] += a[i] * b[j];
        }
        __syncthreads();
    }

    // ---- epilogue
#pragma unroll
    for (int i = 0; i < TM; i++) {
#pragma unroll
        for (int j = 0; j < TN; j += 4) {
            float4 r;
            r.x = acc[i][j + 0]; r.y = acc[i][j + 1];
            r.z = acc[i][j + 2]; r.w = acc[i][j + 3];
            if (BIAS) {
                r.x += __ldg(&bias[colC + j + 0]);
                r.y += __ldg(&bias[colC + j + 1]);
                r.z += __ldg(&bias[colC + j + 2]);
                r.w += __ldg(&bias[colC + j + 3]);
            }
            *reinterpret_cast<float4*>(&C[(long)(rowC + i) * ldc + colC + j]) = r;
        }
    }
}

// ---------------------------------------------------------------------------
// Row softmax over S: rows of length 1024. One block (256 thr) per row.
// p = exp(SCALE*(s - max)) / sum
// ---------------------------------------------------------------------------
__global__ void __launch_bounds__(256) softmax_k(float* __restrict__ S)
{
    const long row = blockIdx.x;
    float4* p = reinterpret_cast<float4*>(S + row * (long)M_);
    float4 v = p[threadIdx.x];

    __shared__ float red[8];
    const int lane = threadIdx.x & 31, w = threadIdx.x >> 5;

    // max
    float m = fmaxf(fmaxf(v.x, v.y), fmaxf(v.z, v.w));
#pragma unroll
    for (int o = 16; o; o >>= 1) m = fmaxf(m, __shfl_xor_sync(~0u, m, o));
    if (lane == 0) red[w] = m;
    __syncthreads();
    m = red[0];
#pragma unroll
    for (int i = 1; i < 8; i++) m = fmaxf(m, red[i]);
    __syncthreads();

    // exp + sum
    v.x = __expf(SCALE_ * (v.x - m));
    v.y = __expf(SCALE_ * (v.y - m));
    v.z = __expf(SCALE_ * (v.z - m));
    v.w = __expf(SCALE_ * (v.w - m));
    float s = v.x + v.y + v.z + v.w;
#pragma unroll
    for (int o = 16; o; o >>= 1) s += __shfl_xor_sync(~0u, s, o);
    if (lane == 0) red[w] = s;
    __syncthreads();
    s = red[0] + red[1] + red[2] + red[3] + red[4] + red[5] + red[6] + red[7];

    const float inv = 1.0f / s;
    v.x *= inv; v.y *= inv; v.z *= inv; v.w *= inv;
    p[threadIdx.x] = v;
}

// ---------------------------------------------------------------------------
extern "C" void kernel_launch(void* const* d_in, const int* in_sizes, int n_in,
                              void* d_out, int out_size)
{
    const float* x    = (const float*)d_in[0];
    const float* ctx  = (const float*)d_in[1];
    const float* Wq   = (const float*)d_in[2];
    const float* Wk   = (const float*)d_in[3];
    const float* Wv   = (const float*)d_in[4];
    const float* Wout = (const float*)d_in[5];
    const float* bout = (const float*)d_in[6];
    float* out = (float*)d_out;

    float *q, *k, *v, *s, *o;
    cudaGetSymbolAddress((void**)&q, g_q);
    cudaGetSymbolAddress((void**)&k, g_k);
    cudaGetSymbolAddress((void**)&v, g_v);
    cudaGetSymbolAddress((void**)&s, g_s);
    cudaGetSymbolAddress((void**)&o, g_o);

    // 1) Q = x @ Wq           [8192,512] = [8192,1024][1024,512]
    sgemm_k<128, 128, 16, 8, 8, false, false><<<dim3(4, 64, 1), 256>>>(
        x, Wq, q, nullptr, QD_, QD_, INNER_, INNER_, 0, 0, 0, 0, 0, 0);

    // 2) K = ctx @ Wk         [4096,512] = [4096,768][768,512]
    sgemm_k<128, 128, 16, 8, 8, false, false><<<dim3(4, 32, 1), 256>>>(
        ctx, Wk, k, nullptr, CD_, CD_, INNER_, INNER_, 0, 0, 0, 0, 0, 0);

    // 3) V = ctx @ Wv
    sgemm_k<128, 128, 16, 8, 8, false, false><<<dim3(4, 32, 1), 256>>>(
        ctx, Wv, v, nullptr, CD_, CD_, INNER_, INNER_, 0, 0, 0, 0, 0, 0);

    // 4) S[z] = Q[b,:,h,:] @ K[b,:,h,:]^T  (z = b*8+h), M=2048,N=1024,K=64
    sgemm_k<128, 128, 16, 8, 8, true, false><<<dim3(8, 16, 32), 256>>>(
        q, k, s, nullptr, D_,
        /*lda*/ INNER_, /*ldb*/ INNER_, /*ldc*/ M_,
        /*sAb*/ (long)N_ * INNER_, /*sAh*/ D_,
        /*sBb*/ (long)M_ * INNER_, /*sBh*/ D_,
        /*sCb*/ (long)H_ * N_ * M_, /*sCh*/ (long)N_ * M_);

    // 5) softmax over 32*2048 rows of 1024
    softmax_k<<<B_ * H_ * N_, 256>>>(s);

    // 6) O[b,:,h,:] = P[z] @ V[b,:,h,:]   M=2048,N=64,K=1024
    sgemm_k<128, 64, 16, 8, 4, false, false><<<dim3(1, 16, 32), 256>>>(
        s, v, o, nullptr, M_,
        /*lda*/ M_, /*ldb*/ INNER_, /*ldc*/ INNER_,
        /*sAb*/ (long)H_ * N_ * M_, /*sAh*/ (long)N_ * M_,
        /*sBb*/ (long)M_ * INNER_, /*sBh*/ D_,
        /*sCb*/ (long)N_ * INNER_, /*sCh*/ D_);

    // 7) out = O @ Wout + bout   [8192,1024] = [8192,512][512,1024]
    sgemm_k<128, 128, 16, 8, 8, false, true><<<dim3(8, 64, 1), 256>>>(
        o, Wout, out, bout, INNER_, INNER_, QD_, QD_, 0, 0, 0, 0, 0, 0);
}

// round 2
// speedup vs baseline: 1.0582x; 1.0582x over previous
#include <cuda_runtime.h>
#include <cstdint>

// ---------------------------------------------------------------------------
// CrossAttention via tf32 tensor-core GEMMs (mma.m16n8k8).
// b=4, n=2048, m=1024, qd=1024, cd=768, heads=8, dim_head=64, inner=512
// ---------------------------------------------------------------------------

#define B_     4
#define N_     2048
#define M_     1024
#define QD_    1024
#define CD_    768
#define H_     8
#define D_     64
#define INNER_ 512
#define SCALE_ 0.125f   // 64^-0.5

// Scratch (device globals: allocation-free rule)
__device__ __align__(16) static float g_q[(size_t)B_ * N_ * INNER_];
__device__ __align__(16) static float g_k[(size_t)B_ * M_ * INNER_];
__device__ __align__(16) static float g_v[(size_t)B_ * M_ * INNER_];
__device__ __align__(16) static float g_s[(size_t)B_ * H_ * N_ * M_];
__device__ __align__(16) static float g_o[(size_t)B_ * N_ * INNER_];

// round f32 -> tf32 (rna) keeping bits in a float
__device__ __forceinline__ float tf32r(float x) {
    uint32_t u;
    asm("cvt.rna.tf32.f32 %0, %1;" : "=r"(u) : "f"(x));
    return __uint_as_float(u);
}

__device__ __forceinline__ void mma_tf32(float c[4], const float a[4], const float b[2]) {
    const uint32_t* A = reinterpret_cast<const uint32_t*>(a);
    const uint32_t* B = reinterpret_cast<const uint32_t*>(b);
    asm volatile(
        "mma.sync.aligned.m16n8k8.row.col.f32.tf32.tf32.f32 "
        "{%0,%1,%2,%3}, {%4,%5,%6,%7}, {%8,%9}, {%0,%1,%2,%3};\n"
        : "+f"(c[0]), "+f"(c[1]), "+f"(c[2]), "+f"(c[3])
        : "r"(A[0]), "r"(A[1]), "r"(A[2]), "r"(A[3]), "r"(B[0]), "r"(B[1]));
}

// ---------------------------------------------------------------------------
// tf32 tensor-core GEMM.
//   TB=false: C[M,N] = A[M,K](lda) * B[K,N](ldb)
//   TB=true : C[M,N] = A[M,K](lda) * B[N,K](ldb)^T
// Batched via grid.z: z -> (zb=z/8, zh=z%8): base += zb*s?b + zh*s?h.
// Dims divide tile sizes exactly for this problem.
// Smem layout: As[BM][BK+4] row-major (m,k), Bs[BN][BK+4] (n,k) -- both
// k-contiguous, matching mma.row.col fragment needs; +4 pad kills conflicts.
// ---------------------------------------------------------------------------
template <int BM, int BN, int BK, int WM, int WN, bool TB, bool BIAS>
__global__ void __launch_bounds__((BM / WM) * (BN / WN) * 32)
mma_gemm(const float* __restrict__ A, const float* __restrict__ Bp,
         float* __restrict__ C, const float* __restrict__ bias,
         int K, int lda, int ldb, int ldc,
         long sAb, long sAh, long sBb, long sBh, long sCb, long sCh)
{
    constexpr int WARPS_M = BM / WM;
    constexpr int WARPS_N = BN / WN;
    constexpr int THREADS = WARPS_M * WARPS_N * 32;
    constexpr int MT = WM / 16;
    constexpr int NT = WN / 8;
    constexpr int LDK = BK + 4;

    const int z  = blockIdx.z;
    const int zb = z >> 3, zh = z & 7;
    A  += (long)zb * sAb + (long)zh * sAh;
    Bp += (long)zb * sBb + (long)zh * sBh;
    C  += (long)zb * sCb + (long)zh * sCh;

    __shared__ float As[BM][LDK];
    __shared__ float Bs[BN][LDK];

    const int tid  = threadIdx.x;
    const int w    = tid >> 5;
    const int lane = tid & 31;
    const int wm   = w / WARPS_N;
    const int wn   = w % WARPS_N;
    const int g    = lane >> 2;   // groupID 0..7
    const int tg   = lane & 3;    // thread-in-group 0..3

    float acc[MT][NT][4];
#pragma unroll
    for (int i = 0; i < MT; i++)
#pragma unroll
        for (int j = 0; j < NT; j++)
#pragma unroll
            for (int t = 0; t < 4; t++) acc[i][j][t] = 0.f;

    for (int k0 = 0; k0 < K; k0 += BK) {
        // ---- A tile: As[m][k]
#pragma unroll
        for (int i = tid; i < BM * (BK / 4); i += THREADS) {
            int r  = i / (BK / 4);
            int c4 = (i % (BK / 4)) * 4;
            float4 t = *reinterpret_cast<const float4*>(
                &A[(long)(blockIdx.y * BM + r) * lda + k0 + c4]);
            As[r][c4 + 0] = tf32r(t.x); As[r][c4 + 1] = tf32r(t.y);
            As[r][c4 + 2] = tf32r(t.z); As[r][c4 + 3] = tf32r(t.w);
        }
        // ---- B tile: Bs[n][k]
        if (TB) {
#pragma unroll
            for (int i = tid; i < BN * (BK / 4); i += THREADS) {
                int r  = i / (BK / 4);
                int c4 = (i % (BK / 4)) * 4;
                float4 t = *reinterpret_cast<const float4*>(
                    &Bp[(long)(blockIdx.x * BN + r) * ldb + k0 + c4]);
                Bs[r][c4 + 0] = tf32r(t.x); Bs[r][c4 + 1] = tf32r(t.y);
                Bs[r][c4 + 2] = tf32r(t.z); Bs[r][c4 + 3] = tf32r(t.w);
            }
        } else {
#pragma unroll
            for (int i = tid; i < BK * (BN / 4); i += THREADS) {
                int r  = i / (BN / 4);        // k
                int c4 = (i % (BN / 4)) * 4;  // n
                float4 t = *reinterpret_cast<const float4*>(
                    &Bp[(long)(k0 + r) * ldb + blockIdx.x * BN + c4]);
                Bs[c4 + 0][r] = tf32r(t.x); Bs[c4 + 1][r] = tf32r(t.y);
                Bs[c4 + 2][r] = tf32r(t.z); Bs[c4 + 3][r] = tf32r(t.w);
            }
        }
        __syncthreads();

        // ---- compute: KT = BK/8 mma k-steps
#pragma unroll
        for (int kk = 0; kk < BK; kk += 8) {
            float a[MT][4];
#pragma unroll
            for (int mi = 0; mi < MT; mi++) {
                int r0 = wm * WM + mi * 16;
                a[mi][0] = As[r0 + g    ][kk + tg];
                a[mi][1] = As[r0 + g + 8][kk + tg];
                a[mi][2] = As[r0 + g    ][kk + tg + 4];
                a[mi][3] = As[r0 + g + 8][kk + tg + 4];
            }
            float b[NT][2];
#pragma unroll
            for (int ni = 0; ni < NT; ni++) {
                int c0 = wn * WN + ni * 8;
                b[ni][0] = Bs[c0 + g][kk + tg];
                b[ni][1] = Bs[c0 + g][kk + tg + 4];
            }
#pragma unroll
            for (int mi = 0; mi < MT; mi++)
#pragma unroll
                for (int ni = 0; ni < NT; ni++)
                    mma_tf32(acc[mi][ni], a[mi], b[ni]);
        }
        __syncthreads();
    }

    // ---- epilogue
#pragma unroll
    for (int mi = 0; mi < MT; mi++) {
        int r0 = blockIdx.y * BM + wm * WM + mi * 16 + g;
#pragma unroll
        for (int ni = 0; ni < NT; ni++) {
            int c0 = blockIdx.x * BN + wn * WN + ni * 8 + tg * 2;
            float2 v0 = make_float2(acc[mi][ni][0], acc[mi][ni][1]);
            float2 v1 = make_float2(acc[mi][ni][2], acc[mi][ni][3]);
            if (BIAS) {
                float b0 = __ldg(&bias[c0]), b1 = __ldg(&bias[c0 + 1]);
                v0.x += b0; v0.y += b1; v1.x += b0; v1.y += b1;
            }
            *reinterpret_cast<float2*>(&C[(long)r0 * ldc + c0])       = v0;
            *reinterpret_cast<float2*>(&C[(long)(r0 + 8) * ldc + c0]) = v1;
        }
    }
}

// ---------------------------------------------------------------------------
// Row softmax: rows of length 1024, one 256-thread block per row.
// p = exp(SCALE*(s - max)) / sum
// ---------------------------------------------------------------------------
__global__ void __launch_bounds__(256) softmax_k(float* __restrict__ S)
{
    const long row = blockIdx.x;
    float4* p = reinterpret_cast<float4*>(S + row * (long)M_);
    float4 v = p[threadIdx.x];

    __shared__ float red[8];
    const int lane = threadIdx.x & 31, w = threadIdx.x >> 5;

    float m = fmaxf(fmaxf(v.x, v.y), fmaxf(v.z, v.w));
#pragma unroll
    for (int o = 16; o; o >>= 1) m = fmaxf(m, __shfl_xor_sync(~0u, m, o));
    if (lane == 0) red[w] = m;
    __syncthreads();
    m = red[0];
#pragma unroll
    for (int i = 1; i < 8; i++) m = fmaxf(m, red[i]);
    __syncthreads();

    v.x = __expf(SCALE_ * (v.x - m));
    v.y = __expf(SCALE_ * (v.y - m));
    v.z = __expf(SCALE_ * (v.z - m));
    v.w = __expf(SCALE_ * (v.w - m));
    float s = v.x + v.y + v.z + v.w;
#pragma unroll
    for (int o = 16; o; o >>= 1) s += __shfl_xor_sync(~0u, s, o);
    if (lane == 0) red[w] = s;
    __syncthreads();
    s = red[0] + red[1] + red[2] + red[3] + red[4] + red[5] + red[6] + red[7];

    const float inv = 1.0f / s;
    v.x *= inv; v.y *= inv; v.z *= inv; v.w *= inv;
    p[threadIdx.x] = v;
}

// ---------------------------------------------------------------------------
extern "C" void kernel_launch(void* const* d_in, const int* in_sizes, int n_in,
                              void* d_out, int out_size)
{
    const float* x    = (const float*)d_in[0];
    const float* ctx  = (const float*)d_in[1];
    const float* Wq   = (const float*)d_in[2];
    const float* Wk   = (const float*)d_in[3];
    const float* Wv   = (const float*)d_in[4];
    const float* Wout = (const float*)d_in[5];
    const float* bout = (const float*)d_in[6];
    float* out = (float*)d_out;

    float *q, *k, *v, *s, *o;
    cudaGetSymbolAddress((void**)&q, g_q);
    cudaGetSymbolAddress((void**)&k, g_k);
    cudaGetSymbolAddress((void**)&v, g_v);
    cudaGetSymbolAddress((void**)&s, g_s);
    cudaGetSymbolAddress((void**)&o, g_o);

    // 1) Q = x @ Wq            [8192,512]
    mma_gemm<128, 128, 16, 64, 32, false, false><<<dim3(4, 64, 1), 256>>>(
        x, Wq, q, nullptr, QD_, QD_, INNER_, INNER_, 0, 0, 0, 0, 0, 0);

    // 2) K = ctx @ Wk          [4096,512]
    mma_gemm<128, 128, 16, 64, 32, false, false><<<dim3(4, 32, 1), 256>>>(
        ctx, Wk, k, nullptr, CD_, CD_, INNER_, INNER_, 0, 0, 0, 0, 0, 0);

    // 3) V = ctx @ Wv
    mma_gemm<128, 128, 16, 64, 32, false, false><<<dim3(4, 32, 1), 256>>>(
        ctx, Wv, v, nullptr, CD_, CD_, INNER_, INNER_, 0, 0, 0, 0, 0, 0);

    // 4) S[z] = Q_head @ K_head^T   (z = b*8+h), M=2048,N=1024,K=64
    mma_gemm<128, 128, 16, 64, 32, true, false><<<dim3(8, 16, 32), 256>>>(
        q, k, s, nullptr, D_,
        INNER_, INNER_, M_,
        (long)N_ * INNER_, D_,
        (long)M_ * INNER_, D_,
        (long)H_ * N_ * M_, (long)N_ * M_);

    // 5) softmax over 32*2048 rows of 1024
    softmax_k<<<B_ * H_ * N_, 256>>>(s);

    // 6) O_head = P[z] @ V_head     M=2048,N=64,K=1024
    mma_gemm<128, 64, 16, 32, 32, false, false><<<dim3(1, 16, 32), 256>>>(
        s, v, o, nullptr, M_,
        M_, INNER_, INNER_,
        (long)H_ * N_ * M_, (long)N_ * M_,
        (long)M_ * INNER_, D_,
        (long)N_ * INNER_, D_);

    // 7) out = O @ Wout + bout      [8192,1024]
    mma_gemm<128, 128, 16, 64, 32, false, true><<<dim3(8, 64, 1), 256>>>(
        o, Wout, out, bout, INNER_, INNER_, QD_, QD_, 0, 0, 0, 0, 0, 0);
}

// round 3
// speedup vs baseline: 2.0498x; 1.9371x over previous
#include <cuda_runtime.h>
#include <cstdint>

// ---------------------------------------------------------------------------
// CrossAttention, tf32 tensor cores + fused flash attention.
// b=4, n=2048, m=1024, qd=1024, cd=768, heads=8, dim_head=64, inner=512
// ---------------------------------------------------------------------------

#define B_     4
#define N_     2048
#define M_     1024
#define QD_    1024
#define CD_    768
#define H_     8
#define D_     64
#define INNER_ 512
#define SCALE_ 0.125f   // 64^-0.5

// Scratch (device globals: allocation-free rule)
__device__ __align__(16) static float g_q[(size_t)B_ * N_ * INNER_];
__device__ __align__(16) static float g_k[(size_t)B_ * M_ * INNER_];
__device__ __align__(16) static float g_v[(size_t)B_ * M_ * INNER_];
__device__ __align__(16) static float g_o[(size_t)B_ * N_ * INNER_];

// round f32 -> tf32 (rna) keeping bits in a float
__device__ __forceinline__ float tf32r(float x) {
    uint32_t u;
    asm("cvt.rna.tf32.f32 %0, %1;" : "=r"(u) : "f"(x));
    return __uint_as_float(u);
}

__device__ __forceinline__ void mma_tf32(float c[4], const float a[4], const float b[2]) {
    const uint32_t* A = reinterpret_cast<const uint32_t*>(a);
    const uint32_t* B = reinterpret_cast<const uint32_t*>(b);
    asm volatile(
        "mma.sync.aligned.m16n8k8.row.col.f32.tf32.tf32.f32 "
        "{%0,%1,%2,%3}, {%4,%5,%6,%7}, {%8,%9}, {%0,%1,%2,%3};\n"
        : "+f"(c[0]), "+f"(c[1]), "+f"(c[2]), "+f"(c[3])
        : "r"(A[0]), "r"(A[1]), "r"(A[2]), "r"(A[3]), "r"(B[0]), "r"(B[1]));
}

// ---------------------------------------------------------------------------
// tf32 tensor-core GEMM (projections).
//   TB=false: C[M,N] = A[M,K](lda) * B[K,N](ldb)
// ---------------------------------------------------------------------------
template <int BM, int BN, int BK, int WM, int WN, bool TB, bool BIAS>
__global__ void __launch_bounds__((BM / WM) * (BN / WN) * 32)
mma_gemm(const float* __restrict__ A, const float* __restrict__ Bp,
         float* __restrict__ C, const float* __restrict__ bias,
         int K, int lda, int ldb, int ldc)
{
    constexpr int WARPS_M = BM / WM;
    constexpr int WARPS_N = BN / WN;
    constexpr int THREADS = WARPS_M * WARPS_N * 32;
    constexpr int MT = WM / 16;
    constexpr int NT = WN / 8;
    constexpr int LDK = BK + 4;

    __shared__ float As[BM][LDK];
    __shared__ float Bs[BN][LDK];

    const int tid  = threadIdx.x;
    const int w    = tid >> 5;
    const int lane = tid & 31;
    const int wm   = w / WARPS_N;
    const int wn   = w % WARPS_N;
    const int g    = lane >> 2;
    const int tg   = lane & 3;

    float acc[MT][NT][4];
#pragma unroll
    for (int i = 0; i < MT; i++)
#pragma unroll
        for (int j = 0; j < NT; j++)
#pragma unroll
            for (int t = 0; t < 4; t++) acc[i][j][t] = 0.f;

    for (int k0 = 0; k0 < K; k0 += BK) {
#pragma unroll
        for (int i = tid; i < BM * (BK / 4); i += THREADS) {
            int r  = i / (BK / 4);
            int c4 = (i % (BK / 4)) * 4;
            float4 t = *reinterpret_cast<const float4*>(
                &A[(long)(blockIdx.y * BM + r) * lda + k0 + c4]);
            As[r][c4 + 0] = tf32r(t.x); As[r][c4 + 1] = tf32r(t.y);
            As[r][c4 + 2] = tf32r(t.z); As[r][c4 + 3] = tf32r(t.w);
        }
        if (TB) {
#pragma unroll
            for (int i = tid; i < BN * (BK / 4); i += THREADS) {
                int r  = i / (BK / 4);
                int c4 = (i % (BK / 4)) * 4;
                float4 t = *reinterpret_cast<const float4*>(
                    &Bp[(long)(blockIdx.x * BN + r) * ldb + k0 + c4]);
                Bs[r][c4 + 0] = tf32r(t.x); Bs[r][c4 + 1] = tf32r(t.y);
                Bs[r][c4 + 2] = tf32r(t.z); Bs[r][c4 + 3] = tf32r(t.w);
            }
        } else {
#pragma unroll
            for (int i = tid; i < BK * (BN / 4); i += THREADS) {
                int r  = i / (BN / 4);
                int c4 = (i % (BN / 4)) * 4;
                float4 t = *reinterpret_cast<const float4*>(
                    &Bp[(long)(k0 + r) * ldb + blockIdx.x * BN + c4]);
                Bs[c4 + 0][r] = tf32r(t.x); Bs[c4 + 1][r] = tf32r(t.y);
                Bs[c4 + 2][r] = tf32r(t.z); Bs[c4 + 3][r] = tf32r(t.w);
            }
        }
        __syncthreads();

#pragma unroll
        for (int kk = 0; kk < BK; kk += 8) {
            float a[MT][4];
#pragma unroll
            for (int mi = 0; mi < MT; mi++) {
                int r0 = wm * WM + mi * 16;
                a[mi][0] = As[r0 + g    ][kk + tg];
                a[mi][1] = As[r0 + g + 8][kk + tg];
                a[mi][2] = As[r0 + g    ][kk + tg + 4];
                a[mi][3] = As[r0 + g + 8][kk + tg + 4];
            }
            float b[NT][2];
#pragma unroll
            for (int ni = 0; ni < NT; ni++) {
                int c0 = wn * WN + ni * 8;
                b[ni][0] = Bs[c0 + g][kk + tg];
                b[ni][1] = Bs[c0 + g][kk + tg + 4];
            }
#pragma unroll
            for (int mi = 0; mi < MT; mi++)
#pragma unroll
                for (int ni = 0; ni < NT; ni++)
                    mma_tf32(acc[mi][ni], a[mi], b[ni]);
        }
        __syncthreads();
    }

#pragma unroll
    for (int mi = 0; mi < MT; mi++) {
        int r0 = blockIdx.y * BM + wm * WM + mi * 16 + g;
#pragma unroll
        for (int ni = 0; ni < NT; ni++) {
            int c0 = blockIdx.x * BN + wn * WN + ni * 8 + tg * 2;
            float2 v0 = make_float2(acc[mi][ni][0], acc[mi][ni][1]);
            float2 v1 = make_float2(acc[mi][ni][2], acc[mi][ni][3]);
            if (BIAS) {
                float b0 = __ldg(&bias[c0]), b1 = __ldg(&bias[c0 + 1]);
                v0.x += b0; v0.y += b1; v1.x += b0; v1.y += b1;
            }
            *reinterpret_cast<float2*>(&C[(long)r0 * ldc + c0])       = v0;
            *reinterpret_cast<float2*>(&C[(long)(r0 + 8) * ldc + c0]) = v1;
        }
    }
}

// ---------------------------------------------------------------------------
// Fused flash attention: per CTA = one (b,h), 128 q-rows.
// 8 warps x 16 q-rows each (warp-exclusive rows -> warp-local softmax stats).
// Q frags in registers (scale folded in); K/V tiles (64 keys) staged in smem.
// P -> A-fragment layout fixed with quad shuffles (no smem round trip).
// O = softmax(Q K^T) V written to g_o in [b,n,h,d] layout.
// ---------------------------------------------------------------------------
__global__ void __launch_bounds__(256) flash_attn_k(
    const float* __restrict__ Q, const float* __restrict__ K,
    const float* __restrict__ V, float* __restrict__ O)
{
    __shared__ float Ks[64][68];   // stride 68: QK^T B-frag LDS conflict-free
    __shared__ float Vs[64][72];   // stride 72: PV   B-frag LDS conflict-free

    const int qt = blockIdx.x;           // q tile (0..15)
    const int z  = blockIdx.y;           // b*8 + h
    const int b  = z >> 3, h = z & 7;
    const int tid = threadIdx.x;
    const int wid = tid >> 5;
    const int lane = tid & 31;
    const int g  = lane >> 2;
    const int tg = lane & 3;

    const float* Qb = Q + (long)b * N_ * INNER_ + h * D_;
    const float* Kb = K + (long)b * M_ * INNER_ + h * D_;
    const float* Vb = V + (long)b * M_ * INNER_ + h * D_;

    // ---- Q fragments (row-scaled by SCALE_, exact since 2^-3)
    float aq[8][4];
    {
        const int r0 = qt * 128 + wid * 16 + g;
#pragma unroll
        for (int kc = 0; kc < 8; kc++) {
            const int c = kc * 8 + tg;
            aq[kc][0] = tf32r(SCALE_ * __ldg(&Qb[(long)r0 * INNER_ + c]));
            aq[kc][1] = tf32r(SCALE_ * __ldg(&Qb[(long)(r0 + 8) * INNER_ + c]));
            aq[kc][2] = tf32r(SCALE_ * __ldg(&Qb[(long)r0 * INNER_ + c + 4]));
            aq[kc][3] = tf32r(SCALE_ * __ldg(&Qb[(long)(r0 + 8) * INNER_ + c + 4]));
        }
    }

    float m0 = -1e30f, m1 = -1e30f, l0 = 0.f, l1 = 0.f;
    float o[8][4];
#pragma unroll
    for (int ni = 0; ni < 8; ni++)
#pragma unroll
        for (int t = 0; t < 4; t++) o[ni][t] = 0.f;

    for (int j0 = 0; j0 < M_; j0 += 64) {
        __syncthreads();   // all warps done reading prev Ks/Vs
        // ---- stage K,V tiles (64 x 64)
#pragma unroll
        for (int i = tid; i < 64 * 16; i += 256) {
            int r = i >> 4, c4 = (i & 15) * 4;
            float4 t = *reinterpret_cast<const float4*>(
                &Kb[(long)(j0 + r) * INNER_ + c4]);
            Ks[r][c4 + 0] = tf32r(t.x); Ks[r][c4 + 1] = tf32r(t.y);
            Ks[r][c4 + 2] = tf32r(t.z); Ks[r][c4 + 3] = tf32r(t.w);
            float4 u = *reinterpret_cast<const float4*>(
                &Vb[(long)(j0 + r) * INNER_ + c4]);
            Vs[r][c4 + 0] = tf32r(u.x); Vs[r][c4 + 1] = tf32r(u.y);
            Vs[r][c4 + 2] = tf32r(u.z); Vs[r][c4 + 3] = tf32r(u.w);
        }
        __syncthreads();

        // ---- S = (scaled Q) K^T : 16 rows x 64 keys per warp
        float s[8][4];
#pragma unroll
        for (int ni = 0; ni < 8; ni++)
#pragma unroll
            for (int t = 0; t < 4; t++) s[ni][t] = 0.f;
#pragma unroll
        for (int kc = 0; kc < 8; kc++) {
#pragma unroll
            for (int ni = 0; ni < 8; ni++) {
                float bb[2];
                bb[0] = Ks[ni * 8 + g][kc * 8 + tg];
                bb[1] = Ks[ni * 8 + g][kc * 8 + tg + 4];
                mma_tf32(s[ni], aq[kc], bb);
            }
        }

        // ---- online softmax (rows g and g+8 of this warp's 16)
        float rm0 = -1e30f, rm1 = -1e30f;
#pragma unroll
        for (int ni = 0; ni < 8; ni++) {
            rm0 = fmaxf(rm0, fmaxf(s[ni][0], s[ni][1]));
            rm1 = fmaxf(rm1, fmaxf(s[ni][2], s[ni][3]));
        }
#pragma unroll
        for (int off = 1; off <= 2; off <<= 1) {
            rm0 = fmaxf(rm0, __shfl_xor_sync(~0u, rm0, off));
            rm1 = fmaxf(rm1, __shfl_xor_sync(~0u, rm1, off));
        }
        const float mn0 = fmaxf(m0, rm0), mn1 = fmaxf(m1, rm1);
        const float cf0 = __expf(m0 - mn0), cf1 = __expf(m1 - mn1);

        float rs0 = 0.f, rs1 = 0.f;
#pragma unroll
        for (int ni = 0; ni < 8; ni++) {
            s[ni][0] = tf32r(__expf(s[ni][0] - mn0));
            s[ni][1] = tf32r(__expf(s[ni][1] - mn0));
            s[ni][2] = tf32r(__expf(s[ni][2] - mn1));
            s[ni][3] = tf32r(__expf(s[ni][3] - mn1));
            rs0 += s[ni][0] + s[ni][1];
            rs1 += s[ni][2] + s[ni][3];
        }
#pragma unroll
        for (int off = 1; off <= 2; off <<= 1) {
            rs0 += __shfl_xor_sync(~0u, rs0, off);
            rs1 += __shfl_xor_sync(~0u, rs1, off);
        }
        l0 = l0 * cf0 + rs0;
        l1 = l1 * cf1 + rs1;
        m0 = mn0; m1 = mn1;
#pragma unroll
        for (int ni = 0; ni < 8; ni++) {
            o[ni][0] *= cf0; o[ni][1] *= cf0;
            o[ni][2] *= cf1; o[ni][3] *= cf1;
        }

        // ---- O += P V  (A frags of P gathered by quad shuffles)
        const int src0 = (lane & 28) | (tg >> 1);
        const int src1 = src0 + 2;
#pragma unroll
        for (int kc = 0; kc < 8; kc++) {
            float x0 = __shfl_sync(~0u, s[kc][0], src0);
            float x1 = __shfl_sync(~0u, s[kc][1], src0);
            float y0 = __shfl_sync(~0u, s[kc][2], src0);
            float y1 = __shfl_sync(~0u, s[kc][3], src0);
            float z0 = __shfl_sync(~0u, s[kc][0], src1);
            float z1 = __shfl_sync(~0u, s[kc][1], src1);
            float u0 = __shfl_sync(~0u, s[kc][2], src1);
            float u1 = __shfl_sync(~0u, s[kc][3], src1);
            float ap[4];
            ap[0] = (tg & 1) ? x1 : x0;
            ap[1] = (tg & 1) ? y1 : y0;
            ap[2] = (tg & 1) ? z1 : z0;
            ap[3] = (tg & 1) ? u1 : u0;
#pragma unroll
            for (int ni = 0; ni < 8; ni++) {
                float bb[2];
                bb[0] = Vs[kc * 8 + tg    ][ni * 8 + g];
                bb[1] = Vs[kc * 8 + tg + 4][ni * 8 + g];
                mma_tf32(o[ni], ap, bb);
            }
        }
    }

    // ---- epilogue: normalize and store
    const float inv0 = 1.0f / l0, inv1 = 1.0f / l1;
    const int r0 = qt * 128 + wid * 16 + g;
    float* Ob = O + (long)b * N_ * INNER_ + h * D_;
#pragma unroll
    for (int ni = 0; ni < 8; ni++) {
        const int c0 = ni * 8 + tg * 2;
        float2 v0 = make_float2(o[ni][0] * inv0, o[ni][1] * inv0);
        float2 v1 = make_float2(o[ni][2] * inv1, o[ni][3] * inv1);
        *reinterpret_cast<float2*>(&Ob[(long)r0 * INNER_ + c0])       = v0;
        *reinterpret_cast<float2*>(&Ob[(long)(r0 + 8) * INNER_ + c0]) = v1;
    }
}

// ---------------------------------------------------------------------------
extern "C" void kernel_launch(void* const* d_in, const int* in_sizes, int n_in,
                              void* d_out, int out_size)
{
    const float* x    = (const float*)d_in[0];
    const float* ctx  = (const float*)d_in[1];
    const float* Wq   = (const float*)d_in[2];
    const float* Wk   = (const float*)d_in[3];
    const float* Wv   = (const float*)d_in[4];
    const float* Wout = (const float*)d_in[5];
    const float* bout = (const float*)d_in[6];
    float* out = (float*)d_out;

    float *q, *k, *v, *o;
    cudaGetSymbolAddress((void**)&q, g_q);
    cudaGetSymbolAddress((void**)&k, g_k);
    cudaGetSymbolAddress((void**)&v, g_v);
    cudaGetSymbolAddress((void**)&o, g_o);

    // 1) Q = x @ Wq            [8192,512]
    mma_gemm<128, 128, 16, 64, 32, false, false><<<dim3(4, 64, 1), 256>>>(
        x, Wq, q, nullptr, QD_, QD_, INNER_, INNER_);

    // 2) K = ctx @ Wk          [4096,512]
    mma_gemm<128, 128, 16, 64, 32, false, false><<<dim3(4, 32, 1), 256>>>(
        ctx, Wk, k, nullptr, CD_, CD_, INNER_, INNER_);

    // 3) V = ctx @ Wv
    mma_gemm<128, 128, 16, 64, 32, false, false><<<dim3(4, 32, 1), 256>>>(
        ctx, Wv, v, nullptr, CD_, CD_, INNER_, INNER_);

    // 4) fused attention: O = softmax(Q K^T * scale) V
    flash_attn_k<<<dim3(16, 32), 256>>>(q, k, v, o);

    // 5) out = O @ Wout + bout  [8192,1024]
    mma_gemm<128, 128, 16, 64, 32, false, true><<<dim3(8, 64, 1), 256>>>(
        o, Wout, out, bout, INNER_, INNER_, QD_, QD_);
}

// round 4
// speedup vs baseline: 2.0710x; 1.0103x over previous
#include <cuda_runtime.h>
#include <cstdint>

// ---------------------------------------------------------------------------
// CrossAttention: tf32 tensor cores, cp.async+ldmatrix pipelined GEMMs,
// fused flash attention. All operands pre-rounded to tf32 in memory.
// b=4, n=2048, m=1024, qd=1024, cd=768, heads=8, dim_head=64, inner=512
// ---------------------------------------------------------------------------

#define B_     4
#define N_     2048
#define M_     1024
#define QD_    1024
#define CD_    768
#define H_     8
#define D_     64
#define INNER_ 512
#define SCALE_ 0.125f   // 64^-0.5

// Scratch (device globals: allocation-free rule)
__device__ __align__(16) static float g_xr[(size_t)B_ * N_ * QD_];     // 32 MB
__device__ __align__(16) static float g_cr[(size_t)B_ * M_ * CD_];     // 12 MB
__device__ __align__(16) static float g_wqt[(size_t)INNER_ * QD_];
__device__ __align__(16) static float g_wkt[(size_t)INNER_ * CD_];
__device__ __align__(16) static float g_wvt[(size_t)INNER_ * CD_];
__device__ __align__(16) static float g_wot[(size_t)QD_ * INNER_];
__device__ __align__(16) static float g_q[(size_t)B_ * N_ * INNER_];
__device__ __align__(16) static float g_k[(size_t)B_ * M_ * INNER_];
__device__ __align__(16) static float g_v[(size_t)B_ * M_ * INNER_];
__device__ __align__(16) static float g_o[(size_t)B_ * N_ * INNER_];

__device__ __forceinline__ float tf32r(float x) {
    uint32_t u;
    asm("cvt.rna.tf32.f32 %0, %1;" : "=r"(u) : "f"(x));
    return __uint_as_float(u);
}

__device__ __forceinline__ uint32_t smem_u32(const void* p) {
    return (uint32_t)__cvta_generic_to_shared(p);
}

__device__ __forceinline__ void cp16(uint32_t saddr, const void* g) {
    asm volatile("cp.async.cg.shared.global [%0], [%1], 16;\n" :: "r"(saddr), "l"(g));
}

__device__ __forceinline__ void ldsm4(uint32_t& r0, uint32_t& r1, uint32_t& r2,
                                      uint32_t& r3, uint32_t addr) {
    asm volatile("ldmatrix.sync.aligned.m8n8.x4.shared.b16 {%0,%1,%2,%3}, [%4];"
                 : "=r"(r0), "=r"(r1), "=r"(r2), "=r"(r3) : "r"(addr));
}

__device__ __forceinline__ void mma_tf32_u(float c[4], const uint32_t a[4],
                                           const uint32_t b[2]) {
    asm volatile(
        "mma.sync.aligned.m16n8k8.row.col.f32.tf32.tf32.f32 "
        "{%0,%1,%2,%3}, {%4,%5,%6,%7}, {%8,%9}, {%0,%1,%2,%3};\n"
        : "+f"(c[0]), "+f"(c[1]), "+f"(c[2]), "+f"(c[3])
        : "r"(a[0]), "r"(a[1]), "r"(a[2]), "r"(a[3]), "r"(b[0]), "r"(b[1]));
}

__device__ __forceinline__ void mma_tf32(float c[4], const float a[4], const float b[2]) {
    const uint32_t* A = reinterpret_cast<const uint32_t*>(a);
    const uint32_t* B = reinterpret_cast<const uint32_t*>(b);
    asm volatile(
        "mma.sync.aligned.m16n8k8.row.col.f32.tf32.tf32.f32 "
        "{%0,%1,%2,%3}, {%4,%5,%6,%7}, {%8,%9}, {%0,%1,%2,%3};\n"
        : "+f"(c[0]), "+f"(c[1]), "+f"(c[2]), "+f"(c[3])
        : "r"(A[0]), "r"(A[1]), "r"(A[2]), "r"(A[3]), "r"(B[0]), "r"(B[1]));
}

// ---------------------------------------------------------------------------
// Prep: tf32-round copy (float4) and transpose+round for weights.
// ---------------------------------------------------------------------------
__global__ void __launch_bounds__(256) round_copy_k(
    const float4* __restrict__ in, float4* __restrict__ out, int n4)
{
    int i = blockIdx.x * 256 + threadIdx.x;
    if (i < n4) {
        float4 t = in[i];
        t.x = tf32r(t.x); t.y = tf32r(t.y); t.z = tf32r(t.z); t.w = tf32r(t.w);
        out[i] = t;
    }
}

// W[K][N] -> Wt[N][K] with tf32 rounding. grid (N/32, K/32), block (32,8).
__global__ void __launch_bounds__(256) transpose_round_k(
    const float* __restrict__ W, float* __restrict__ Wt, int K, int N)
{
    __shared__ float t[32][33];
    const int n0 = blockIdx.x * 32, k0 = blockIdx.y * 32;
    const int tx = threadIdx.x, ty = threadIdx.y;
#pragma unroll
    for (int j = 0; j < 32; j += 8)
        t[ty + j][tx] = W[(long)(k0 + ty + j) * N + n0 + tx];
    __syncthreads();
#pragma unroll
    for (int j = 0; j < 32; j += 8)
        Wt[(long)(n0 + ty + j) * K + k0 + tx] = tf32r(t[tx][ty + j]);
}

// ---------------------------------------------------------------------------
// Pipelined tf32 GEMM: C[M][N] = A[M][K] * Bt[N][K]^T (+bias).
// BM=BN=128, BK=16, 8 warps (warp tile 64x32), cp.async 2-stage,
// ldmatrix.x4 fragment loads, all data pre-rounded tf32 (no cvt in loop).
// Smem rows padded to 20 floats -> LDSM & cp.async conflict-free.
// grid = (N/128, M/128). All dims divide exactly.
// ---------------------------------------------------------------------------
template <bool BIAS, bool ROUND_OUT>
__global__ void __launch_bounds__(256) gemm_tt(
    const float* __restrict__ A, const float* __restrict__ Bt,
    float* __restrict__ C, const float* __restrict__ bias, int Kd, int ldc)
{
    __shared__ float As[2][128 * 20];
    __shared__ float Bs[2][128 * 20];

    const int tid  = threadIdx.x;
    const int lane = tid & 31;
    const int w    = tid >> 5;
    const int wm   = w >> 2;       // 0..1
    const int wn   = w & 3;        // 0..3
    const int g    = lane >> 2;
    const int tg   = lane & 3;

    const uint32_t sA = smem_u32(As), sB = smem_u32(Bs);
    const uint32_t SO = 128 * 20 * 4;   // stage byte stride

    // ldmatrix base addresses (kk=0, stage 0)
    const uint32_t aA = sA + ((((wm * 64 + (lane & 15)) * 20) + (lane >> 4) * 4) << 2);
    const uint32_t aB = sB + ((((wn * 32 + ((lane >> 4) << 3) + (lane & 7)) * 20)
                               + ((lane >> 3) & 1) * 4) << 2);

    // staging: thread handles rows r1, r1+64 at k-chunk c1 (A and B)
    const int r1 = tid >> 2;
    const int c1 = (tid & 3) * 4;
    const float* gA1 = A  + (long)(blockIdx.y * 128 + r1) * Kd + c1;
    const float* gA2 = gA1 + (long)64 * Kd;
    const float* gB1 = Bt + (long)(blockIdx.x * 128 + r1) * Kd + c1;
    const float* gB2 = gB1 + (long)64 * Kd;
    const uint32_t stA1 = sA + ((r1 * 20 + c1) << 2);
    const uint32_t stA2 = stA1 + (64 * 20 << 2);
    const uint32_t stB1 = sB + ((r1 * 20 + c1) << 2);
    const uint32_t stB2 = stB1 + (64 * 20 << 2);

    float acc[4][4][4];
#pragma unroll
    for (int i = 0; i < 4; i++)
#pragma unroll
        for (int j = 0; j < 4; j++)
#pragma unroll
            for (int t = 0; t < 4; t++) acc[i][j][t] = 0.f;

    const int T = Kd >> 4;

    // prologue: stage 0
    cp16(stA1, gA1); cp16(stA2, gA2);
    cp16(stB1, gB1); cp16(stB2, gB2);
    asm volatile("cp.async.commit_group;\n");

    for (int t = 0; t < T; t++) {
        if (t + 1 < T) {
            const int k0 = (t + 1) << 4;
            const uint32_t o = ((t + 1) & 1) * SO;
            cp16(stA1 + o, gA1 + k0); cp16(stA2 + o, gA2 + k0);
            cp16(stB1 + o, gB1 + k0); cp16(stB2 + o, gB2 + k0);
            asm volatile("cp.async.commit_group;\n");
            asm volatile("cp.async.wait_group 1;\n");
        } else {
            asm volatile("cp.async.wait_group 0;\n");
        }
        __syncthreads();

        const uint32_t so = (t & 1) * SO;
#pragma unroll
        for (int kk = 0; kk < 2; kk++) {
            const uint32_t ko = so + kk * 32;   // 8 floats = 32B
            uint32_t a[4][4], b[4][2];
#pragma unroll
            for (int mi = 0; mi < 4; mi++)
                ldsm4(a[mi][0], a[mi][1], a[mi][2], a[mi][3],
                      aA + ko + mi * (16 * 20 * 4));
#pragma unroll
            for (int p = 0; p < 2; p++)
                ldsm4(b[2 * p][0], b[2 * p][1], b[2 * p + 1][0], b[2 * p + 1][1],
                      aB + ko + p * (16 * 20 * 4));
#pragma unroll
            for (int mi = 0; mi < 4; mi++)
#pragma unroll
                for (int ni = 0; ni < 4; ni++)
                    mma_tf32_u(acc[mi][ni], a[mi], b[ni]);
        }
        __syncthreads();
    }

    // epilogue
#pragma unroll
    for (int mi = 0; mi < 4; mi++) {
        const int r0 = blockIdx.y * 128 + wm * 64 + mi * 16 + g;
#pragma unroll
        for (int ni = 0; ni < 4; ni++) {
            const int c0 = blockIdx.x * 128 + wn * 32 + ni * 8 + tg * 2;
            float2 v0 = make_float2(acc[mi][ni][0], acc[mi][ni][1]);
            float2 v1 = make_float2(acc[mi][ni][2], acc[mi][ni][3]);
            if (BIAS) {
                float b0 = __ldg(&bias[c0]), b1 = __ldg(&bias[c0 + 1]);
                v0.x += b0; v0.y += b1; v1.x += b0; v1.y += b1;
            }
            if (ROUND_OUT) {
                v0.x = tf32r(v0.x); v0.y = tf32r(v0.y);
                v1.x = tf32r(v1.x); v1.y = tf32r(v1.y);
            }
            *reinterpret_cast<float2*>(&C[(long)r0 * ldc + c0])       = v0;
            *reinterpret_cast<float2*>(&C[(long)(r0 + 8) * ldc + c0]) = v1;
        }
    }
}

// ---------------------------------------------------------------------------
// Fused flash attention: per CTA = one (b,h), 128 q-rows.
// Q/K/V pre-rounded tf32 in memory (no cvt in staging).
// ---------------------------------------------------------------------------
__global__ void __launch_bounds__(256) flash_attn_k(
    const float* __restrict__ Q, const float* __restrict__ K,
    const float* __restrict__ V, float* __restrict__ O)
{
    __shared__ float Ks[64][68];
    __shared__ float Vs[64][72];

    const int qt = blockIdx.x;
    const int z  = blockIdx.y;
    const int b  = z >> 3, h = z & 7;
    const int tid = threadIdx.x;
    const int wid = tid >> 5;
    const int lane = tid & 31;
    const int g  = lane >> 2;
    const int tg = lane & 3;

    const float* Qb = Q + (long)b * N_ * INNER_ + h * D_;
    const float* Kb = K + (long)b * M_ * INNER_ + h * D_;
    const float* Vb = V + (long)b * M_ * INNER_ + h * D_;

    float aq[8][4];
    {
        const int r0 = qt * 128 + wid * 16 + g;
#pragma unroll
        for (int kc = 0; kc < 8; kc++) {
            const int c = kc * 8 + tg;
            aq[kc][0] = SCALE_ * __ldg(&Qb[(long)r0 * INNER_ + c]);
            aq[kc][1] = SCALE_ * __ldg(&Qb[(long)(r0 + 8) * INNER_ + c]);
            aq[kc][2] = SCALE_ * __ldg(&Qb[(long)r0 * INNER_ + c + 4]);
            aq[kc][3] = SCALE_ * __ldg(&Qb[(long)(r0 + 8) * INNER_ + c + 4]);
        }
    }

    float m0 = -1e30f, m1 = -1e30f, l0 = 0.f, l1 = 0.f;
    float o[8][4];
#pragma unroll
    for (int ni = 0; ni < 8; ni++)
#pragma unroll
        for (int t = 0; t < 4; t++) o[ni][t] = 0.f;

    for (int j0 = 0; j0 < M_; j0 += 64) {
        __syncthreads();
#pragma unroll
        for (int i = tid; i < 64 * 16; i += 256) {
            int r = i >> 4, c4 = (i & 15) * 4;
            *reinterpret_cast<float4*>(&Ks[r][c4]) =
                *reinterpret_cast<const float4*>(&Kb[(long)(j0 + r) * INNER_ + c4]);
            *reinterpret_cast<float4*>(&Vs[r][c4]) =
                *reinterpret_cast<const float4*>(&Vb[(long)(j0 + r) * INNER_ + c4]);
        }
        __syncthreads();

        float s[8][4];
#pragma unroll
        for (int ni = 0; ni < 8; ni++)
#pragma unroll
            for (int t = 0; t < 4; t++) s[ni][t] = 0.f;
#pragma unroll
        for (int kc = 0; kc < 8; kc++) {
#pragma unroll
            for (int ni = 0; ni < 8; ni++) {
                float bb[2];
                bb[0] = Ks[ni * 8 + g][kc * 8 + tg];
                bb[1] = Ks[ni * 8 + g][kc * 8 + tg + 4];
                mma_tf32(s[ni], aq[kc], bb);
            }
        }

        float rm0 = -1e30f, rm1 = -1e30f;
#pragma unroll
        for (int ni = 0; ni < 8; ni++) {
            rm0 = fmaxf(rm0, fmaxf(s[ni][0], s[ni][1]));
            rm1 = fmaxf(rm1, fmaxf(s[ni][2], s[ni][3]));
        }
#pragma unroll
        for (int off = 1; off <= 2; off <<= 1) {
            rm0 = fmaxf(rm0, __shfl_xor_sync(~0u, rm0, off));
            rm1 = fmaxf(rm1, __shfl_xor_sync(~0u, rm1, off));
        }
        const float mn0 = fmaxf(m0, rm0), mn1 = fmaxf(m1, rm1);
        const float cf0 = __expf(m0 - mn0), cf1 = __expf(m1 - mn1);

        float rs0 = 0.f, rs1 = 0.f;
#pragma unroll
        for (int ni = 0; ni < 8; ni++) {
            s[ni][0] = tf32r(__expf(s[ni][0] - mn0));
            s[ni][1] = tf32r(__expf(s[ni][1] - mn0));
            s[ni][2] = tf32r(__expf(s[ni][2] - mn1));
            s[ni][3] = tf32r(__expf(s[ni][3] - mn1));
            rs0 += s[ni][0] + s[ni][1];
            rs1 += s[ni][2] + s[ni][3];
        }
#pragma unroll
        for (int off = 1; off <= 2; off <<= 1) {
            rs0 += __shfl_xor_sync(~0u, rs0, off);
            rs1 += __shfl_xor_sync(~0u, rs1, off);
        }
        l0 = l0 * cf0 + rs0;
        l1 = l1 * cf1 + rs1;
        m0 = mn0; m1 = mn1;
#pragma unroll
        for (int ni = 0; ni < 8; ni++) {
            o[ni][0] *= cf0; o[ni][1] *= cf0;
            o[ni][2] *= cf1; o[ni][3] *= cf1;
        }

        const int src0 = (lane & 28) | (tg >> 1);
        const int src1 = src0 + 2;
#pragma unroll
        for (int kc = 0; kc < 8; kc++) {
            float x0 = __shfl_sync(~0u, s[kc][0], src0);
            float x1 = __shfl_sync(~0u, s[kc][1], src0);
            float y0 = __shfl_sync(~0u, s[kc][2], src0);
            float y1 = __shfl_sync(~0u, s[kc][3], src0);
            float z0 = __shfl_sync(~0u, s[kc][0], src1);
            float z1 = __shfl_sync(~0u, s[kc][1], src1);
            float u0 = __shfl_sync(~0u, s[kc][2], src1);
            float u1 = __shfl_sync(~0u, s[kc][3], src1);
            float ap[4];
            ap[0] = (tg & 1) ? x1 : x0;
            ap[1] = (tg & 1) ? y1 : y0;
            ap[2] = (tg & 1) ? z1 : z0;
            ap[3] = (tg & 1) ? u1 : u0;
#pragma unroll
            for (int ni = 0; ni < 8; ni++) {
                float bb[2];
                bb[0] = Vs[kc * 8 + tg    ][ni * 8 + g];
                bb[1] = Vs[kc * 8 + tg + 4][ni * 8 + g];
                mma_tf32(o[ni], ap, bb);
            }
        }
    }

    const float inv0 = 1.0f / l0, inv1 = 1.0f / l1;
    const int r0 = qt * 128 + wid * 16 + g;
    float* Ob = O + (long)b * N_ * INNER_ + h * D_;
#pragma unroll
    for (int ni = 0; ni < 8; ni++) {
        const int c0 = ni * 8 + tg * 2;
        float2 v0 = make_float2(tf32r(o[ni][0] * inv0), tf32r(o[ni][1] * inv0));
        float2 v1 = make_float2(tf32r(o[ni][2] * inv1), tf32r(o[ni][3] * inv1));
        *reinterpret_cast<float2*>(&Ob[(long)r0 * INNER_ + c0])       = v0;
        *reinterpret_cast<float2*>(&Ob[(long)(r0 + 8) * INNER_ + c0]) = v1;
    }
}

// ---------------------------------------------------------------------------
extern "C" void kernel_launch(void* const* d_in, const int* in_sizes, int n_in,
                              void* d_out, int out_size)
{
    const float* x    = (const float*)d_in[0];
    const float* ctx  = (const float*)d_in[1];
    const float* Wq   = (const float*)d_in[2];
    const float* Wk   = (const float*)d_in[3];
    const float* Wv   = (const float*)d_in[4];
    const float* Wout = (const float*)d_in[5];
    const float* bout = (const float*)d_in[6];
    float* out = (float*)d_out;

    float *xr, *cr, *wqt, *wkt, *wvt, *wot, *q, *k, *v, *o;
    cudaGetSymbolAddress((void**)&xr,  g_xr);
    cudaGetSymbolAddress((void**)&cr,  g_cr);
    cudaGetSymbolAddress((void**)&wqt, g_wqt);
    cudaGetSymbolAddress((void**)&wkt, g_wkt);
    cudaGetSymbolAddress((void**)&wvt, g_wvt);
    cudaGetSymbolAddress((void**)&wot, g_wot);
    cudaGetSymbolAddress((void**)&q,   g_q);
    cudaGetSymbolAddress((void**)&k,   g_k);
    cudaGetSymbolAddress((void**)&v,   g_v);
    cudaGetSymbolAddress((void**)&o,   g_o);

    // ---- prep: tf32-round activations, transpose+round weights
    {
        int n4x = B_ * N_ * QD_ / 4;   // 2097152
        round_copy_k<<<(n4x + 255) / 256, 256>>>((const float4*)x, (float4*)xr, n4x);
        int n4c = B_ * M_ * CD_ / 4;   // 786432
        round_copy_k<<<(n4c + 255) / 256, 256>>>((const float4*)ctx, (float4*)cr, n4c);
        transpose_round_k<<<dim3(INNER_ / 32, QD_ / 32), dim3(32, 8)>>>(Wq, wqt, QD_, INNER_);
        transpose_round_k<<<dim3(INNER_ / 32, CD_ / 32), dim3(32, 8)>>>(Wk, wkt, CD_, INNER_);
        transpose_round_k<<<dim3(INNER_ / 32, CD_ / 32), dim3(32, 8)>>>(Wv, wvt, CD_, INNER_);
        transpose_round_k<<<dim3(QD_ / 32, INNER_ / 32), dim3(32, 8)>>>(Wout, wot, INNER_, QD_);
    }

    // ---- projections
    gemm_tt<false, true><<<dim3(INNER_ / 128, B_ * N_ / 128), 256>>>(
        xr, wqt, q, nullptr, QD_, INNER_);
    gemm_tt<false, true><<<dim3(INNER_ / 128, B_ * M_ / 128), 256>>>(
        cr, wkt, k, nullptr, CD_, INNER_);
    gemm_tt<false, true><<<dim3(INNER_ / 128, B_ * M_ / 128), 256>>>(
        cr, wvt, v, nullptr, CD_, INNER_);

    // ---- fused attention
    flash_attn_k<<<dim3(16, 32), 256>>>(q, k, v, o);

    // ---- output projection (+bias), full-precision store
    gemm_tt<true, false><<<dim3(QD_ / 128, B_ * N_ / 128), 256>>>(
        o, wot, out, bout, INNER_, QD_);
}

// round 6
// speedup vs baseline: 2.6126x; 1.2615x over previous
#include <cuda_runtime.h>
#include <cstdint>

// ---------------------------------------------------------------------------
// CrossAttention: mma.sync tf32 GEMMs (3-stage cp.async, 64x64 warp tiles,
// ldmatrix) + fused flash attention. All operands pre-rounded to tf32.
// b=4, n=2048, m=1024, qd=1024, cd=768, heads=8, dim_head=64, inner=512
// ---------------------------------------------------------------------------

#define B_     4
#define N_     2048
#define M_     1024
#define QD_    1024
#define CD_    768
#define H_     8
#define D_     64
#define INNER_ 512
#define KV_LD  1024
#define SCALE_ 0.125f   // 64^-0.5

// Scratch (device globals: allocation-free rule)
__device__ __align__(16) static float g_xr[(size_t)B_ * N_ * QD_];
__device__ __align__(16) static float g_cr[(size_t)B_ * M_ * CD_];
__device__ __align__(16) static float g_wqt[(size_t)INNER_ * QD_];
__device__ __align__(16) static float g_wkvt[(size_t)2 * INNER_ * CD_];  // [Wk^T; Wv^T]
__device__ __align__(16) static float g_wot[(size_t)QD_ * INNER_];
__device__ __align__(16) static float g_q[(size_t)B_ * N_ * INNER_];
__device__ __align__(16) static float g_kv[(size_t)B_ * M_ * KV_LD];    // K | V
__device__ __align__(16) static float g_o[(size_t)B_ * N_ * INNER_];

__device__ __forceinline__ float tf32r(float x) {
    uint32_t u;
    asm("cvt.rna.tf32.f32 %0, %1;" : "=r"(u) : "f"(x));
    return __uint_as_float(u);
}
__device__ __forceinline__ uint32_t smem_u32(const void* p) {
    return (uint32_t)__cvta_generic_to_shared(p);
}
__device__ __forceinline__ void cp16(uint32_t saddr, const void* g) {
    asm volatile("cp.async.cg.shared.global [%0], [%1], 16;\n" :: "r"(saddr), "l"(g));
}
__device__ __forceinline__ void ldsm4(uint32_t& r0, uint32_t& r1, uint32_t& r2,
                                      uint32_t& r3, uint32_t addr) {
    asm volatile("ldmatrix.sync.aligned.m8n8.x4.shared.b16 {%0,%1,%2,%3}, [%4];"
                 : "=r"(r0), "=r"(r1), "=r"(r2), "=r"(r3) : "r"(addr));
}
__device__ __forceinline__ void mma_tf32_u(float c[4], const uint32_t a[4],
                                           const uint32_t b[2]) {
    asm volatile(
        "mma.sync.aligned.m16n8k8.row.col.f32.tf32.tf32.f32 "
        "{%0,%1,%2,%3}, {%4,%5,%6,%7}, {%8,%9}, {%0,%1,%2,%3};\n"
        : "+f"(c[0]), "+f"(c[1]), "+f"(c[2]), "+f"(c[3])
        : "r"(a[0]), "r"(a[1]), "r"(a[2]), "r"(a[3]), "r"(b[0]), "r"(b[1]));
}
__device__ __forceinline__ void mma_tf32(float c[4], const float a[4], const float b[2]) {
    const uint32_t* A = reinterpret_cast<const uint32_t*>(a);
    const uint32_t* B = reinterpret_cast<const uint32_t*>(b);
    asm volatile(
        "mma.sync.aligned.m16n8k8.row.col.f32.tf32.tf32.f32 "
        "{%0,%1,%2,%3}, {%4,%5,%6,%7}, {%8,%9}, {%0,%1,%2,%3};\n"
        : "+f"(c[0]), "+f"(c[1]), "+f"(c[2]), "+f"(c[3])
        : "r"(A[0]), "r"(A[1]), "r"(A[2]), "r"(A[3]), "r"(B[0]), "r"(B[1]));
}

// ---------------------------------------------------------------------------
// Prep kernels
// ---------------------------------------------------------------------------
__global__ void __launch_bounds__(256) round_copy_k(
    const float4* __restrict__ in, float4* __restrict__ out, int n4)
{
    int i = blockIdx.x * 256 + threadIdx.x;
    if (i < n4) {
        float4 t = in[i];
        t.x = tf32r(t.x); t.y = tf32r(t.y); t.z = tf32r(t.z); t.w = tf32r(t.w);
        out[i] = t;
    }
}

// W[K][N] -> Wt[N][K] with tf32 rounding. grid (N/32, K/32), block (32,8).
__global__ void __launch_bounds__(256) transpose_round_k(
    const float* __restrict__ W, float* __restrict__ Wt, int K, int N)
{
    __shared__ float t[32][33];
    const int n0 = blockIdx.x * 32, k0 = blockIdx.y * 32;
    const int tx = threadIdx.x, ty = threadIdx.y;
#pragma unroll
    for (int j = 0; j < 32; j += 8)
        t[ty + j][tx] = W[(long)(k0 + ty + j) * N + n0 + tx];
    __syncthreads();
#pragma unroll
    for (int j = 0; j < 32; j += 8)
        Wt[(long)(n0 + ty + j) * K + k0 + tx] = tf32r(t[tx][ty + j]);
}

// ---------------------------------------------------------------------------
// tf32 GEMM: C[M][N] = A[M][K] * Bt[N][K]^T (+bias).
// CTA tile 128x128, 4 warps (warp tile 64x64), BK=16,
// 3-stage cp.async, ONE __syncthreads per K-chunk, ldmatrix.x4 frags.
// Stage layout (floats): A[128][20] then B[128][20]; stage stride 5120 floats.
// grid = (N/128, M/128); dims divide exactly.
// ---------------------------------------------------------------------------
#define STG_F   5120                 // floats per stage
#define STG_B   (STG_F * 4)          // bytes per stage (20480)
#define GEMM_SMEM (3 * STG_B)        // 61440 B

template <bool BIAS, bool ROUND_OUT>
__global__ void __launch_bounds__(128) gemm_tc(
    const float* __restrict__ A, const float* __restrict__ Bt,
    float* __restrict__ C, const float* __restrict__ bias, int Kd, int ldc)
{
    extern __shared__ float sm[];
    const uint32_t sb = smem_u32(sm);

    const int tid  = threadIdx.x;
    const int lane = tid & 31;
    const int w    = tid >> 5;
    const int wm   = w >> 1;      // 0..1
    const int wn   = w & 1;       // 0..1
    const int g    = lane >> 2;
    const int tg   = lane & 3;

    // ldmatrix base addrs (relative to stage start)
    const uint32_t aA = ((((wm * 64 + (lane & 15)) * 20) + (lane >> 4) * 4) << 2);
    const uint32_t aB = ((((wn * 64 + ((lane >> 4) << 3) + (lane & 7)) * 20)
                          + ((lane >> 3) & 1) * 4) << 2) + 128 * 20 * 4;

    // staging: thread -> row tid, 4 x 16B chunks
    const float* gA = A  + (long)(blockIdx.y * 128 + tid) * Kd;
    const float* gB = Bt + (long)(blockIdx.x * 128 + tid) * Kd;
    const uint32_t stA = sb + ((tid * 20) << 2);
    const uint32_t stB = stA + 128 * 20 * 4;

    float acc[4][8][4];
#pragma unroll
    for (int i = 0; i < 4; i++)
#pragma unroll
        for (int j = 0; j < 8; j++)
#pragma unroll
            for (int t = 0; t < 4; t++) acc[i][j][t] = 0.f;

    const int T = Kd >> 4;

    // prologue: stages 0,1
#pragma unroll
    for (int s = 0; s < 2; s++) {
        const uint32_t so = s * STG_B;
        const int k0 = s * 16;
#pragma unroll
        for (int c = 0; c < 4; c++) {
            cp16(stA + so + (c << 4), gA + k0 + c * 4);
            cp16(stB + so + (c << 4), gB + k0 + c * 4);
        }
        asm volatile("cp.async.commit_group;\n");
    }

    int buf = 0;          // t % 3
    int pbuf = 2;         // (t+2) % 3
    for (int t = 0; t < T; t++) {
        if (t == T - 1) asm volatile("cp.async.wait_group 0;\n");
        else            asm volatile("cp.async.wait_group 1;\n");
        __syncthreads();

        if (t + 2 < T) {
            const uint32_t so = pbuf * STG_B;
            const int k0 = (t + 2) << 4;
#pragma unroll
            for (int c = 0; c < 4; c++) {
                cp16(stA + so + (c << 4), gA + k0 + c * 4);
                cp16(stB + so + (c << 4), gB + k0 + c * 4);
            }
            asm volatile("cp.async.commit_group;\n");
        }

        const uint32_t so = buf * STG_B;
#pragma unroll
        for (int kk = 0; kk < 2; kk++) {
            const uint32_t ko = so + kk * 32;
            uint32_t a[4][4], b[8][2];
#pragma unroll
            for (int mi = 0; mi < 4; mi++)
                ldsm4(a[mi][0], a[mi][1], a[mi][2], a[mi][3],
                      sb + aA + ko + mi * (16 * 20 * 4));
#pragma unroll
            for (int p = 0; p < 4; p++)
                ldsm4(b[2 * p][0], b[2 * p][1], b[2 * p + 1][0], b[2 * p + 1][1],
                      sb + aB + ko + p * (16 * 20 * 4));
#pragma unroll
            for (int mi = 0; mi < 4; mi++)
#pragma unroll
                for (int ni = 0; ni < 8; ni++)
                    mma_tf32_u(acc[mi][ni], a[mi], b[ni]);
        }
        buf  = (buf  == 2) ? 0 : buf + 1;
        pbuf = (pbuf == 2) ? 0 : pbuf + 1;
    }

    // epilogue
#pragma unroll
    for (int mi = 0; mi < 4; mi++) {
        const int r0 = blockIdx.y * 128 + wm * 64 + mi * 16 + g;
#pragma unroll
        for (int ni = 0; ni < 8; ni++) {
            const int c0 = blockIdx.x * 128 + wn * 64 + ni * 8 + tg * 2;
            float2 v0 = make_float2(acc[mi][ni][0], acc[mi][ni][1]);
            float2 v1 = make_float2(acc[mi][ni][2], acc[mi][ni][3]);
            if (BIAS) {
                float b0 = __ldg(&bias[c0]), b1 = __ldg(&bias[c0 + 1]);
                v0.x += b0; v0.y += b1; v1.x += b0; v1.y += b1;
            }
            if (ROUND_OUT) {
                v0.x = tf32r(v0.x); v0.y = tf32r(v0.y);
                v1.x = tf32r(v1.x); v1.y = tf32r(v1.y);
            }
            *reinterpret_cast<float2*>(&C[(long)r0 * ldc + c0])       = v0;
            *reinterpret_cast<float2*>(&C[(long)(r0 + 8) * ldc + c0]) = v1;
        }
    }
}

// ---------------------------------------------------------------------------
// Fused flash attention: per CTA = one (b,h), 128 q-rows.
// K/V read from fused kv buffer (ld = 1024, V at column offset 512).
// ---------------------------------------------------------------------------
__global__ void __launch_bounds__(256) flash_attn_k(
    const float* __restrict__ Q, const float* __restrict__ KV,
    float* __restrict__ O)
{
    __shared__ float Ks[64][68];
    __shared__ float Vs[64][72];

    const int qt = blockIdx.x;
    const int z  = blockIdx.y;
    const int b  = z >> 3, h = z & 7;
    const int tid = threadIdx.x;
    const int wid = tid >> 5;
    const int lane = tid & 31;
    const int g  = lane >> 2;
    const int tg = lane & 3;

    const float* Qb = Q  + (long)b * N_ * INNER_ + h * D_;
    const float* Kb = KV + (long)b * M_ * KV_LD + h * D_;
    const float* Vb = KV + (long)b * M_ * KV_LD + INNER_ + h * D_;

    float aq[8][4];
    {
        const int r0 = qt * 128 + wid * 16 + g;
#pragma unroll
        for (int kc = 0; kc < 8; kc++) {
            const int c = kc * 8 + tg;
            aq[kc][0] = SCALE_ * __ldg(&Qb[(long)r0 * INNER_ + c]);
            aq[kc][1] = SCALE_ * __ldg(&Qb[(long)(r0 + 8) * INNER_ + c]);
            aq[kc][2] = SCALE_ * __ldg(&Qb[(long)r0 * INNER_ + c + 4]);
            aq[kc][3] = SCALE_ * __ldg(&Qb[(long)(r0 + 8) * INNER_ + c + 4]);
        }
    }

    float m0 = -1e30f, m1 = -1e30f, l0 = 0.f, l1 = 0.f;
    float o[8][4];
#pragma unroll
    for (int ni = 0; ni < 8; ni++)
#pragma unroll
        for (int t = 0; t < 4; t++) o[ni][t] = 0.f;

    for (int j0 = 0; j0 < M_; j0 += 64) {
        __syncthreads();
#pragma unroll
        for (int i = tid; i < 64 * 16; i += 256) {
            int r = i >> 4, c4 = (i & 15) * 4;
            *reinterpret_cast<float4*>(&Ks[r][c4]) =
                *reinterpret_cast<const float4*>(&Kb[(long)(j0 + r) * KV_LD + c4]);
            *reinterpret_cast<float4*>(&Vs[r][c4]) =
                *reinterpret_cast<const float4*>(&Vb[(long)(j0 + r) * KV_LD + c4]);
        }
        __syncthreads();

        float s[8][4];
#pragma unroll
        for (int ni = 0; ni < 8; ni++)
#pragma unroll
            for (int t = 0; t < 4; t++) s[ni][t] = 0.f;
#pragma unroll
        for (int kc = 0; kc < 8; kc++) {
#pragma unroll
            for (int ni = 0; ni < 8; ni++) {
                float bb[2];
                bb[0] = Ks[ni * 8 + g][kc * 8 + tg];
                bb[1] = Ks[ni * 8 + g][kc * 8 + tg + 4];
                mma_tf32(s[ni], aq[kc], bb);
            }
        }

        float rm0 = -1e30f, rm1 = -1e30f;
#pragma unroll
        for (int ni = 0; ni < 8; ni++) {
            rm0 = fmaxf(rm0, fmaxf(s[ni][0], s[ni][1]));
            rm1 = fmaxf(rm1, fmaxf(s[ni][2], s[ni][3]));
        }
#pragma unroll
        for (int off = 1; off <= 2; off <<= 1) {
            rm0 = fmaxf(rm0, __shfl_xor_sync(~0u, rm0, off));
            rm1 = fmaxf(rm1, __shfl_xor_sync(~0u, rm1, off));
        }
        const float mn0 = fmaxf(m0, rm0), mn1 = fmaxf(m1, rm1);
        const float cf0 = __expf(m0 - mn0), cf1 = __expf(m1 - mn1);

        float rs0 = 0.f, rs1 = 0.f;
#pragma unroll
        for (int ni = 0; ni < 8; ni++) {
            s[ni][0] = tf32r(__expf(s[ni][0] - mn0));
            s[ni][1] = tf32r(__expf(s[ni][1] - mn0));
            s[ni][2] = tf32r(__expf(s[ni][2] - mn1));
            s[ni][3] = tf32r(__expf(s[ni][3] - mn1));
            rs0 += s[ni][0] + s[ni][1];
            rs1 += s[ni][2] + s[ni][3];
        }
#pragma unroll
        for (int off = 1; off <= 2; off <<= 1) {
            rs0 += __shfl_xor_sync(~0u, rs0, off);
            rs1 += __shfl_xor_sync(~0u, rs1, off);
        }
        l0 = l0 * cf0 + rs0;
        l1 = l1 * cf1 + rs1;
        m0 = mn0; m1 = mn1;
#pragma unroll
        for (int ni = 0; ni < 8; ni++) {
            o[ni][0] *= cf0; o[ni][1] *= cf0;
            o[ni][2] *= cf1; o[ni][3] *= cf1;
        }

        const int src0 = (lane & 28) | (tg >> 1);
        const int src1 = src0 + 2;
#pragma unroll
        for (int kc = 0; kc < 8; kc++) {
            float x0 = __shfl_sync(~0u, s[kc][0], src0);
            float x1 = __shfl_sync(~0u, s[kc][1], src0);
            float y0 = __shfl_sync(~0u, s[kc][2], src0);
            float y1 = __shfl_sync(~0u, s[kc][3], src0);
            float z0 = __shfl_sync(~0u, s[kc][0], src1);
            float z1 = __shfl_sync(~0u, s[kc][1], src1);
            float u0 = __shfl_sync(~0u, s[kc][2], src1);
            float u1 = __shfl_sync(~0u, s[kc][3], src1);
            float ap[4];
            ap[0] = (tg & 1) ? x1 : x0;
            ap[1] = (tg & 1) ? y1 : y0;
            ap[2] = (tg & 1) ? z1 : z0;
            ap[3] = (tg & 1) ? u1 : u0;
#pragma unroll
            for (int ni = 0; ni < 8; ni++) {
                float bb[2];
                bb[0] = Vs[kc * 8 + tg    ][ni * 8 + g];
                bb[1] = Vs[kc * 8 + tg + 4][ni * 8 + g];
                mma_tf32(o[ni], ap, bb);
            }
        }
    }

    const float inv0 = 1.0f / l0, inv1 = 1.0f / l1;
    const int r0 = qt * 128 + wid * 16 + g;
    float* Ob = O + (long)b * N_ * INNER_ + h * D_;
#pragma unroll
    for (int ni = 0; ni < 8; ni++) {
        const int c0 = ni * 8 + tg * 2;
        float2 v0 = make_float2(tf32r(o[ni][0] * inv0), tf32r(o[ni][1] * inv0));
        float2 v1 = make_float2(tf32r(o[ni][2] * inv1), tf32r(o[ni][3] * inv1));
        *reinterpret_cast<float2*>(&Ob[(long)r0 * INNER_ + c0])       = v0;
        *reinterpret_cast<float2*>(&Ob[(long)(r0 + 8) * INNER_ + c0]) = v1;
    }
}

// ---------------------------------------------------------------------------
extern "C" void kernel_launch(void* const* d_in, const int* in_sizes, int n_in,
                              void* d_out, int out_size)
{
    const float* x    = (const float*)d_in[0];
    const float* ctx  = (const float*)d_in[1];
    const float* Wq   = (const float*)d_in[2];
    const float* Wk   = (const float*)d_in[3];
    const float* Wv   = (const float*)d_in[4];
    const float* Wout = (const float*)d_in[5];
    const float* bout = (const float*)d_in[6];
    float* out = (float*)d_out;

    float *xr, *cr, *wqt, *wkvt, *wot, *q, *kv, *o;
    cudaGetSymbolAddress((void**)&xr,   g_xr);
    cudaGetSymbolAddress((void**)&cr,   g_cr);
    cudaGetSymbolAddress((void**)&wqt,  g_wqt);
    cudaGetSymbolAddress((void**)&wkvt, g_wkvt);
    cudaGetSymbolAddress((void**)&wot,  g_wot);
    cudaGetSymbolAddress((void**)&q,    g_q);
    cudaGetSymbolAddress((void**)&kv,   g_kv);
    cudaGetSymbolAddress((void**)&o,    g_o);

    cudaFuncSetAttribute(gemm_tc<false, true>,
                         cudaFuncAttributeMaxDynamicSharedMemorySize, GEMM_SMEM);
    cudaFuncSetAttribute(gemm_tc<true, false>,
                         cudaFuncAttributeMaxDynamicSharedMemorySize, GEMM_SMEM);

    // ---- prep: tf32-round activations; transpose+round weights
    {
        int n4x = B_ * N_ * QD_ / 4;
        round_copy_k<<<(n4x + 255) / 256, 256>>>((const float4*)x, (float4*)xr, n4x);
        int n4c = B_ * M_ * CD_ / 4;
        round_copy_k<<<(n4c + 255) / 256, 256>>>((const float4*)ctx, (float4*)cr, n4c);
        transpose_round_k<<<dim3(INNER_ / 32, QD_ / 32), dim3(32, 8)>>>(Wq, wqt, QD_, INNER_);
        transpose_round_k<<<dim3(INNER_ / 32, CD_ / 32), dim3(32, 8)>>>(Wk, wkvt, CD_, INNER_);
        transpose_round_k<<<dim3(INNER_ / 32, CD_ / 32), dim3(32, 8)>>>(
            Wv, wkvt + (size_t)INNER_ * CD_, CD_, INNER_);
        transpose_round_k<<<dim3(QD_ / 32, INNER_ / 32), dim3(32, 8)>>>(Wout, wot, INNER_, QD_);
    }

    // ---- Q projection: [8192,512]
    gemm_tc<false, true><<<dim3(INNER_ / 128, B_ * N_ / 128), 128, GEMM_SMEM>>>(
        xr, wqt, q, nullptr, QD_, INNER_);

    // ---- fused K|V projection: [4096,1024]
    gemm_tc<false, true><<<dim3(KV_LD / 128, B_ * M_ / 128), 128, GEMM_SMEM>>>(
        cr, wkvt, kv, nullptr, CD_, KV_LD);

    // ---- fused attention
    flash_attn_k<<<dim3(16, 32), 256>>>(q, kv, o);

    // ---- output projection (+bias): [8192,1024]
    gemm_tc<true, false><<<dim3(QD_ / 128, B_ * N_ / 128), 128, GEMM_SMEM>>>(
        o, wot, out, bout, INNER_, QD_);
}

// round 7
// speedup vs baseline: 2.6669x; 1.0208x over previous
#include <cuda_runtime.h>
#include <cstdint>

// ---------------------------------------------------------------------------
// CrossAttention: mma.sync tf32 GEMMs (BK=32, 2-stage cp.async, 64x64 warp
// tiles, ldmatrix) + cp.async double-buffered fused flash attention.
// b=4, n=2048, m=1024, qd=1024, cd=768, heads=8, dim_head=64, inner=512
// ---------------------------------------------------------------------------

#define B_     4
#define N_     2048
#define M_     1024
#define QD_    1024
#define CD_    768
#define H_     8
#define D_     64
#define INNER_ 512
#define KV_LD  1024
#define SCALE_ 0.125f   // 64^-0.5

// Scratch (device globals: allocation-free rule)
__device__ __align__(16) static float g_xr[(size_t)B_ * N_ * QD_];
__device__ __align__(16) static float g_cr[(size_t)B_ * M_ * CD_];
__device__ __align__(16) static float g_wqt[(size_t)INNER_ * QD_];
__device__ __align__(16) static float g_wkvt[(size_t)2 * INNER_ * CD_];  // [Wk^T; Wv^T]
__device__ __align__(16) static float g_wot[(size_t)QD_ * INNER_];
__device__ __align__(16) static float g_q[(size_t)B_ * N_ * INNER_];
__device__ __align__(16) static float g_kv[(size_t)B_ * M_ * KV_LD];    // K | V
__device__ __align__(16) static float g_o[(size_t)B_ * N_ * INNER_];

__device__ __forceinline__ float tf32r(float x) {
    uint32_t u;
    asm("cvt.rna.tf32.f32 %0, %1;" : "=r"(u) : "f"(x));
    return __uint_as_float(u);
}
__device__ __forceinline__ uint32_t smem_u32(const void* p) {
    return (uint32_t)__cvta_generic_to_shared(p);
}
__device__ __forceinline__ void cp16(uint32_t saddr, const void* g) {
    asm volatile("cp.async.cg.shared.global [%0], [%1], 16;\n" :: "r"(saddr), "l"(g));
}
__device__ __forceinline__ void ldsm4(uint32_t& r0, uint32_t& r1, uint32_t& r2,
                                      uint32_t& r3, uint32_t addr) {
    asm volatile("ldmatrix.sync.aligned.m8n8.x4.shared.b16 {%0,%1,%2,%3}, [%4];"
                 : "=r"(r0), "=r"(r1), "=r"(r2), "=r"(r3) : "r"(addr));
}
__device__ __forceinline__ void mma_tf32_u(float c[4], const uint32_t a[4],
                                           const uint32_t b[2]) {
    asm volatile(
        "mma.sync.aligned.m16n8k8.row.col.f32.tf32.tf32.f32 "
        "{%0,%1,%2,%3}, {%4,%5,%6,%7}, {%8,%9}, {%0,%1,%2,%3};\n"
        : "+f"(c[0]), "+f"(c[1]), "+f"(c[2]), "+f"(c[3])
        : "r"(a[0]), "r"(a[1]), "r"(a[2]), "r"(a[3]), "r"(b[0]), "r"(b[1]));
}
__device__ __forceinline__ void mma_tf32(float c[4], const float a[4], const float b[2]) {
    const uint32_t* A = reinterpret_cast<const uint32_t*>(a);
    const uint32_t* B = reinterpret_cast<const uint32_t*>(b);
    asm volatile(
        "mma.sync.aligned.m16n8k8.row.col.f32.tf32.tf32.f32 "
        "{%0,%1,%2,%3}, {%4,%5,%6,%7}, {%8,%9}, {%0,%1,%2,%3};\n"
        : "+f"(c[0]), "+f"(c[1]), "+f"(c[2]), "+f"(c[3])
        : "r"(A[0]), "r"(A[1]), "r"(A[2]), "r"(A[3]), "r"(B[0]), "r"(B[1]));
}

// ---------------------------------------------------------------------------
// Prep: one fused round-copy (x then ctx), one fused 4-way transpose+round.
// ---------------------------------------------------------------------------
__global__ void __launch_bounds__(256) round_copy2_k(
    const float4* __restrict__ a, float4* __restrict__ ao, int n4a,
    const float4* __restrict__ b, float4* __restrict__ bo, int n4b)
{
    int i = blockIdx.x * 256 + threadIdx.x;
    if (i < n4a) {
        float4 t = a[i];
        t.x = tf32r(t.x); t.y = tf32r(t.y); t.z = tf32r(t.z); t.w = tf32r(t.w);
        ao[i] = t;
    } else if (i < n4a + n4b) {
        int j = i - n4a;
        float4 t = b[j];
        t.x = tf32r(t.x); t.y = tf32r(t.y); t.z = tf32r(t.z); t.w = tf32r(t.w);
        bo[j] = t;
    }
}

// z selects matrix. W[K][N] -> Wt[N][K], tf32-rounded.
__global__ void __launch_bounds__(256) transpose_round4_k(
    const float* __restrict__ W0, float* __restrict__ T0,   // Wq   1024x512
    const float* __restrict__ W1, float* __restrict__ T1,   // Wk    768x512
    const float* __restrict__ W2, float* __restrict__ T2,   // Wv    768x512
    const float* __restrict__ W3, float* __restrict__ T3)   // Wout  512x1024
{
    const float* W; float* Tt; int K, N;
    switch (blockIdx.z) {
        case 0:  W = W0; Tt = T0; K = QD_;    N = INNER_; break;
        case 1:  W = W1; Tt = T1; K = CD_;    N = INNER_; break;
        case 2:  W = W2; Tt = T2; K = CD_;    N = INNER_; break;
        default: W = W3; Tt = T3; K = INNER_; N = QD_;    break;
    }
    const int n0 = blockIdx.x * 32, k0 = blockIdx.y * 32;
    if (n0 >= N || k0 >= K) return;

    __shared__ float t[32][33];
    const int tx = threadIdx.x & 31, ty = threadIdx.x >> 5;
#pragma unroll
    for (int j = 0; j < 32; j += 8)
        t[ty + j][tx] = W[(long)(k0 + ty + j) * N + n0 + tx];
    __syncthreads();
#pragma unroll
    for (int j = 0; j < 32; j += 8)
        Tt[(long)(n0 + ty + j) * K + k0 + tx] = tf32r(t[tx][ty + j]);
}

// ---------------------------------------------------------------------------
// tf32 GEMM: C[M][N] = A[M][K] * Bt[N][K]^T (+bias).
// CTA tile 128x128, 4 warps (64x64), BK=32 per stage, 2-stage cp.async,
// ONE __syncthreads per 32-K chunk. Rows padded to 36 floats.
// grid = (N/128, M/128); dims divide exactly.
// ---------------------------------------------------------------------------
#define GSTG_F  (128 * 36 * 2)        // floats per stage (A then B)
#define GSTG_B  (GSTG_F * 4)          // 36864 bytes
#define GEMM_SMEM (2 * GSTG_B)        // 73728 bytes

template <bool BIAS, bool ROUND_OUT>
__global__ void __launch_bounds__(128) gemm_tc(
    const float* __restrict__ A, const float* __restrict__ Bt,
    float* __restrict__ C, const float* __restrict__ bias, int Kd, int ldc)
{
    extern __shared__ float sm[];
    const uint32_t sb = smem_u32(sm);

    const int tid  = threadIdx.x;
    const int lane = tid & 31;
    const int w    = tid >> 5;
    const int wm   = w >> 1;      // 0..1
    const int wn   = w & 1;       // 0..1
    const int g    = lane >> 2;
    const int tg   = lane & 3;

    // ldmatrix base addrs (relative to stage start)
    const uint32_t aA = ((((wm * 64 + (lane & 15)) * 36) + (lane >> 4) * 4) << 2);
    const uint32_t aB = ((((wn * 64 + ((lane >> 4) << 3) + (lane & 7)) * 36)
                          + ((lane >> 3) & 1) * 4) << 2) + 128 * 36 * 4;

    // staging: thread -> row tid of A and of B, 8 x 16B chunks each
    const float* gA = A  + (long)(blockIdx.y * 128 + tid) * Kd;
    const float* gB = Bt + (long)(blockIdx.x * 128 + tid) * Kd;
    const uint32_t stA = sb + ((tid * 36) << 2);
    const uint32_t stB = stA + 128 * 36 * 4;

    float acc[4][8][4];
#pragma unroll
    for (int i = 0; i < 4; i++)
#pragma unroll
        for (int j = 0; j < 8; j++)
#pragma unroll
            for (int t = 0; t < 4; t++) acc[i][j][t] = 0.f;

    const int T = Kd >> 5;

    // prologue: chunk 0 -> stage 0
#pragma unroll
    for (int c = 0; c < 8; c++) {
        cp16(stA + (c << 4), gA + c * 4);
        cp16(stB + (c << 4), gB + c * 4);
    }
    asm volatile("cp.async.commit_group;\n");

    for (int t = 0; t < T; t++) {
        asm volatile("cp.async.wait_group 0;\n");
        __syncthreads();

        if (t + 1 < T) {
            const uint32_t so2 = ((t + 1) & 1) * GSTG_B;
            const int k0 = (t + 1) << 5;
#pragma unroll
            for (int c = 0; c < 8; c++) {
                cp16(stA + so2 + (c << 4), gA + k0 + c * 4);
                cp16(stB + so2 + (c << 4), gB + k0 + c * 4);
            }
            asm volatile("cp.async.commit_group;\n");
        }

        const uint32_t so = (t & 1) * GSTG_B;
#pragma unroll
        for (int kk = 0; kk < 4; kk++) {
            const uint32_t ko = so + kk * 32;
            uint32_t a[4][4], b[8][2];
#pragma unroll
            for (int mi = 0; mi < 4; mi++)
                ldsm4(a[mi][0], a[mi][1], a[mi][2], a[mi][3],
                      sb + aA + ko + mi * (16 * 36 * 4));
#pragma unroll
            for (int p = 0; p < 4; p++)
                ldsm4(b[2 * p][0], b[2 * p][1], b[2 * p + 1][0], b[2 * p + 1][1],
                      sb + aB + ko + p * (16 * 36 * 4));
#pragma unroll
            for (int mi = 0; mi < 4; mi++)
#pragma unroll
                for (int ni = 0; ni < 8; ni++)
                    mma_tf32_u(acc[mi][ni], a[mi], b[ni]);
        }
    }

    // epilogue
#pragma unroll
    for (int mi = 0; mi < 4; mi++) {
        const int r0 = blockIdx.y * 128 + wm * 64 + mi * 16 + g;
#pragma unroll
        for (int ni = 0; ni < 8; ni++) {
            const int c0 = blockIdx.x * 128 + wn * 64 + ni * 8 + tg * 2;
            float2 v0 = make_float2(acc[mi][ni][0], acc[mi][ni][1]);
            float2 v1 = make_float2(acc[mi][ni][2], acc[mi][ni][3]);
            if (BIAS) {
                float b0 = __ldg(&bias[c0]), b1 = __ldg(&bias[c0 + 1]);
                v0.x += b0; v0.y += b1; v1.x += b0; v1.y += b1;
            }
            if (ROUND_OUT) {
                v0.x = tf32r(v0.x); v0.y = tf32r(v0.y);
                v1.x = tf32r(v1.x); v1.y = tf32r(v1.y);
            }
            *reinterpret_cast<float2*>(&C[(long)r0 * ldc + c0])       = v0;
            *reinterpret_cast<float2*>(&C[(long)(r0 + 8) * ldc + c0]) = v1;
        }
    }
}

// ---------------------------------------------------------------------------
// Fused flash attention: per CTA = one (b,h), 128 q-rows, 16 key-tiles of 64.
// cp.async double-buffered K/V staging; one __syncthreads per tile.
// Dynamic smem layout (floats): K stages [2][64*68], then V stages [2][64*72].
// ---------------------------------------------------------------------------
#define FKS  (64 * 68)                  // 4352 floats per K stage
#define FVS  (64 * 72)                  // 4608 floats per V stage
#define FVB  (2 * FKS)                  // V base (floats)
#define FLASH_SMEM ((2 * FKS + 2 * FVS) * 4)   // 71680 bytes

__global__ void __launch_bounds__(256) flash_attn_k(
    const float* __restrict__ Q, const float* __restrict__ KV,
    float* __restrict__ O)
{
    extern __shared__ float fsm[];
    const uint32_t sb = smem_u32(fsm);

    const int qt = blockIdx.x;
    const int z  = blockIdx.y;
    const int b  = z >> 3, h = z & 7;
    const int tid = threadIdx.x;
    const int wid = tid >> 5;
    const int lane = tid & 31;
    const int g  = lane >> 2;
    const int tg = lane & 3;

    const float* Qb = Q  + (long)b * N_ * INNER_ + h * D_;
    const float* Kb = KV + (long)b * M_ * KV_LD + h * D_;
    const float* Vb = KV + (long)b * M_ * KV_LD + INNER_ + h * D_;

    // per-thread staging chunks: 4 K + 4 V rowsets
    const int sr = tid >> 4;            // base row 0..15
    const int sc = (tid & 15) * 4;      // col 0,4,..,60

    // prologue: tile 0 -> stage 0
#pragma unroll
    for (int jj = 0; jj < 4; jj++) {
        const int r = sr + jj * 16;
        cp16(sb + ((r * 68 + sc) << 2),              Kb + (long)r * KV_LD + sc);
        cp16(sb + ((FVB + r * 72 + sc) << 2),        Vb + (long)r * KV_LD + sc);
    }
    asm volatile("cp.async.commit_group;\n");

    float aq[8][4];
    {
        const int r0 = qt * 128 + wid * 16 + g;
#pragma unroll
        for (int kc = 0; kc < 8; kc++) {
            const int c = kc * 8 + tg;
            aq[kc][0] = SCALE_ * __ldg(&Qb[(long)r0 * INNER_ + c]);
            aq[kc][1] = SCALE_ * __ldg(&Qb[(long)(r0 + 8) * INNER_ + c]);
            aq[kc][2] = SCALE_ * __ldg(&Qb[(long)r0 * INNER_ + c + 4]);
            aq[kc][3] = SCALE_ * __ldg(&Qb[(long)(r0 + 8) * INNER_ + c + 4]);
        }
    }

    float m0 = -1e30f, m1 = -1e30f, l0 = 0.f, l1 = 0.f;
    float o[8][4];
#pragma unroll
    for (int ni = 0; ni < 8; ni++)
#pragma unroll
        for (int t = 0; t < 4; t++) o[ni][t] = 0.f;

    for (int jt = 0; jt < 16; jt++) {
        asm volatile("cp.async.wait_group 0;\n");
        __syncthreads();   // tile jt ready; all warps done with stage being refilled

        if (jt + 1 < 16) {
            const int st = (jt + 1) & 1;
            const int j0 = (jt + 1) * 64;
#pragma unroll
            for (int jj = 0; jj < 4; jj++) {
                const int r = sr + jj * 16;
                cp16(sb + (((st * FKS) + r * 68 + sc) << 2),
                     Kb + (long)(j0 + r) * KV_LD + sc);
                cp16(sb + (((FVB + st * FVS) + r * 72 + sc) << 2),
                     Vb + (long)(j0 + r) * KV_LD + sc);
            }
            asm volatile("cp.async.commit_group;\n");
        }

        const float* Ks = fsm + (jt & 1) * FKS;
        const float* Vs = fsm + FVB + (jt & 1) * FVS;

        // ---- S = (scaled Q) K^T
        float s[8][4];
#pragma unroll
        for (int ni = 0; ni < 8; ni++)
#pragma unroll
            for (int t = 0; t < 4; t++) s[ni][t] = 0.f;
#pragma unroll
        for (int kc = 0; kc < 8; kc++) {
#pragma unroll
            for (int ni = 0; ni < 8; ni++) {
                float bb[2];
                bb[0] = Ks[(ni * 8 + g) * 68 + kc * 8 + tg];
                bb[1] = Ks[(ni * 8 + g) * 68 + kc * 8 + tg + 4];
                mma_tf32(s[ni], aq[kc], bb);
            }
        }

        // ---- online softmax
        float rm0 = -1e30f, rm1 = -1e30f;
#pragma unroll
        for (int ni = 0; ni < 8; ni++) {
            rm0 = fmaxf(rm0, fmaxf(s[ni][0], s[ni][1]));
            rm1 = fmaxf(rm1, fmaxf(s[ni][2], s[ni][3]));
        }
#pragma unroll
        for (int off = 1; off <= 2; off <<= 1) {
            rm0 = fmaxf(rm0, __shfl_xor_sync(~0u, rm0, off));
            rm1 = fmaxf(rm1, __shfl_xor_sync(~0u, rm1, off));
        }
        const float mn0 = fmaxf(m0, rm0), mn1 = fmaxf(m1, rm1);
        const float cf0 = __expf(m0 - mn0), cf1 = __expf(m1 - mn1);

        float rs0 = 0.f, rs1 = 0.f;
#pragma unroll
        for (int ni = 0; ni < 8; ni++) {
            s[ni][0] = tf32r(__expf(s[ni][0] - mn0));
            s[ni][1] = tf32r(__expf(s[ni][1] - mn0));
            s[ni][2] = tf32r(__expf(s[ni][2] - mn1));
            s[ni][3] = tf32r(__expf(s[ni][3] - mn1));
            rs0 += s[ni][0] + s[ni][1];
            rs1 += s[ni][2] + s[ni][3];
        }
#pragma unroll
        for (int off = 1; off <= 2; off <<= 1) {
            rs0 += __shfl_xor_sync(~0u, rs0, off);
            rs1 += __shfl_xor_sync(~0u, rs1, off);
        }
        l0 = l0 * cf0 + rs0;
        l1 = l1 * cf1 + rs1;
        m0 = mn0; m1 = mn1;
#pragma unroll
        for (int ni = 0; ni < 8; ni++) {
            o[ni][0] *= cf0; o[ni][1] *= cf0;
            o[ni][2] *= cf1; o[ni][3] *= cf1;
        }

        // ---- O += P V (A frags via quad shuffles)
        const int src0 = (lane & 28) | (tg >> 1);
        const int src1 = src0 + 2;
#pragma unroll
        for (int kc = 0; kc < 8; kc++) {
            float x0 = __shfl_sync(~0u, s[kc][0], src0);
            float x1 = __shfl_sync(~0u, s[kc][1], src0);
            float y0 = __shfl_sync(~0u, s[kc][2], src0);
            float y1 = __shfl_sync(~0u, s[kc][3], src0);
            float z0 = __shfl_sync(~0u, s[kc][0], src1);
            float z1 = __shfl_sync(~0u, s[kc][1], src1);
            float u0 = __shfl_sync(~0u, s[kc][2], src1);
            float u1 = __shfl_sync(~0u, s[kc][3], src1);
            float ap[4];
            ap[0] = (tg & 1) ? x1 : x0;
            ap[1] = (tg & 1) ? y1 : y0;
            ap[2] = (tg & 1) ? z1 : z0;
            ap[3] = (tg & 1) ? u1 : u0;
#pragma unroll
            for (int ni = 0; ni < 8; ni++) {
                float bb[2];
                bb[0] = Vs[(kc * 8 + tg) * 72 + ni * 8 + g];
                bb[1] = Vs[(kc * 8 + tg + 4) * 72 + ni * 8 + g];
                mma_tf32(o[ni], ap, bb);
            }
        }
    }

    const float inv0 = 1.0f / l0, inv1 = 1.0f / l1;
    const int r0 = qt * 128 + wid * 16 + g;
    float* Ob = O + (long)b * N_ * INNER_ + h * D_;
#pragma unroll
    for (int ni = 0; ni < 8; ni++) {
        const int c0 = ni * 8 + tg * 2;
        float2 v0 = make_float2(tf32r(o[ni][0] * inv0), tf32r(o[ni][1] * inv0));
        float2 v1 = make_float2(tf32r(o[ni][2] * inv1), tf32r(o[ni][3] * inv1));
        *reinterpret_cast<float2*>(&Ob[(long)r0 * INNER_ + c0])       = v0;
        *reinterpret_cast<float2*>(&Ob[(long)(r0 + 8) * INNER_ + c0]) = v1;
    }
}

// ---------------------------------------------------------------------------
extern "C" void kernel_launch(void* const* d_in, const int* in_sizes, int n_in,
                              void* d_out, int out_size)
{
    const float* x    = (const float*)d_in[0];
    const float* ctx  = (const float*)d_in[1];
    const float* Wq   = (const float*)d_in[2];
    const float* Wk   = (const float*)d_in[3];
    const float* Wv   = (const float*)d_in[4];
    const float* Wout = (const float*)d_in[5];
    const float* bout = (const float*)d_in[6];
    float* out = (float*)d_out;

    float *xr, *cr, *wqt, *wkvt, *wot, *q, *kv, *o;
    cudaGetSymbolAddress((void**)&xr,   g_xr);
    cudaGetSymbolAddress((void**)&cr,   g_cr);
    cudaGetSymbolAddress((void**)&wqt,  g_wqt);
    cudaGetSymbolAddress((void**)&wkvt, g_wkvt);
    cudaGetSymbolAddress((void**)&wot,  g_wot);
    cudaGetSymbolAddress((void**)&q,    g_q);
    cudaGetSymbolAddress((void**)&kv,   g_kv);
    cudaGetSymbolAddress((void**)&o,    g_o);

    cudaFuncSetAttribute(gemm_tc<false, true>,
                         cudaFuncAttributeMaxDynamicSharedMemorySize, GEMM_SMEM);
    cudaFuncSetAttribute(gemm_tc<true, false>,
                         cudaFuncAttributeMaxDynamicSharedMemorySize, GEMM_SMEM);
    cudaFuncSetAttribute(flash_attn_k,
                         cudaFuncAttributeMaxDynamicSharedMemorySize, FLASH_SMEM);

    // ---- prep: one fused round-copy, one fused 4-way transpose
    {
        const int n4x = B_ * N_ * QD_ / 4;
        const int n4c = B_ * M_ * CD_ / 4;
        round_copy2_k<<<(n4x + n4c + 255) / 256, 256>>>(
            (const float4*)x, (float4*)xr, n4x,
            (const float4*)ctx, (float4*)cr, n4c);
        transpose_round4_k<<<dim3(32, 32, 4), 256>>>(
            Wq, wqt, Wk, wkvt, Wv, wkvt + (size_t)INNER_ * CD_, Wout, wot);
    }

    // ---- Q projection: [8192,512]
    gemm_tc<false, true><<<dim3(INNER_ / 128, B_ * N_ / 128), 128, GEMM_SMEM>>>(
        xr, wqt, q, nullptr, QD_, INNER_);

    // ---- fused K|V projection: [4096,1024]
    gemm_tc<false, true><<<dim3(KV_LD / 128, B_ * M_ / 128), 128, GEMM_SMEM>>>(
        cr, wkvt, kv, nullptr, CD_, KV_LD);

    // ---- fused attention
    flash_attn_k<<<dim3(16, 32), 256, FLASH_SMEM>>>(q, kv, o);

    // ---- output projection (+bias): [8192,1024]
    gemm_tc<true, false><<<dim3(QD_ / 128, B_ * N_ / 128), 128, GEMM_SMEM>>>(
        o, wot, out, bout, INNER_, QD_);
}

// round 8
// speedup vs baseline: 2.6896x; 1.0085x over previous
#include <cuda_runtime.h>
#include <cstdint>

// ---------------------------------------------------------------------------
// CrossAttention: mma.sync tf32 GEMMs (128x64 tiles, 4 CTA/SM, fused QKV
// launch) + cp.async double-buffered fused flash attention.
// b=4, n=2048, m=1024, qd=1024, cd=768, heads=8, dim_head=64, inner=512
// ---------------------------------------------------------------------------

#define B_     4
#define N_     2048
#define M_     1024
#define QD_    1024
#define CD_    768
#define H_     8
#define D_     64
#define INNER_ 512
#define KV_LD  1024
#define SCALE_ 0.125f   // 64^-0.5

// Scratch (device globals: allocation-free rule)
__device__ __align__(16) static float g_xr[(size_t)B_ * N_ * QD_];
__device__ __align__(16) static float g_cr[(size_t)B_ * M_ * CD_];
__device__ __align__(16) static float g_wqt[(size_t)INNER_ * QD_];
__device__ __align__(16) static float g_wkvt[(size_t)2 * INNER_ * CD_];  // [Wk^T; Wv^T]
__device__ __align__(16) static float g_wot[(size_t)QD_ * INNER_];
__device__ __align__(16) static float g_q[(size_t)B_ * N_ * INNER_];
__device__ __align__(16) static float g_kv[(size_t)B_ * M_ * KV_LD];    // K | V
__device__ __align__(16) static float g_o[(size_t)B_ * N_ * INNER_];

__device__ __forceinline__ float tf32r(float x) {
    uint32_t u;
    asm("cvt.rna.tf32.f32 %0, %1;" : "=r"(u) : "f"(x));
    return __uint_as_float(u);
}
__device__ __forceinline__ uint32_t smem_u32(const void* p) {
    return (uint32_t)__cvta_generic_to_shared(p);
}
__device__ __forceinline__ void cp16(uint32_t saddr, const void* g) {
    asm volatile("cp.async.cg.shared.global [%0], [%1], 16;\n" :: "r"(saddr), "l"(g));
}
__device__ __forceinline__ void ldsm4(uint32_t& r0, uint32_t& r1, uint32_t& r2,
                                      uint32_t& r3, uint32_t addr) {
    asm volatile("ldmatrix.sync.aligned.m8n8.x4.shared.b16 {%0,%1,%2,%3}, [%4];"
                 : "=r"(r0), "=r"(r1), "=r"(r2), "=r"(r3) : "r"(addr));
}
__device__ __forceinline__ void mma_tf32_u(float c[4], const uint32_t a[4],
                                           const uint32_t b[2]) {
    asm volatile(
        "mma.sync.aligned.m16n8k8.row.col.f32.tf32.tf32.f32 "
        "{%0,%1,%2,%3}, {%4,%5,%6,%7}, {%8,%9}, {%0,%1,%2,%3};\n"
        : "+f"(c[0]), "+f"(c[1]), "+f"(c[2]), "+f"(c[3])
        : "r"(a[0]), "r"(a[1]), "r"(a[2]), "r"(a[3]), "r"(b[0]), "r"(b[1]));
}
__device__ __forceinline__ void mma_tf32(float c[4], const float a[4], const float b[2]) {
    const uint32_t* A = reinterpret_cast<const uint32_t*>(a);
    const uint32_t* B = reinterpret_cast<const uint32_t*>(b);
    asm volatile(
        "mma.sync.aligned.m16n8k8.row.col.f32.tf32.tf32.f32 "
        "{%0,%1,%2,%3}, {%4,%5,%6,%7}, {%8,%9}, {%0,%1,%2,%3};\n"
        : "+f"(c[0]), "+f"(c[1]), "+f"(c[2]), "+f"(c[3])
        : "r"(A[0]), "r"(A[1]), "r"(A[2]), "r"(A[3]), "r"(B[0]), "r"(B[1]));
}

// ---------------------------------------------------------------------------
// Prep kernels
// ---------------------------------------------------------------------------
__global__ void __launch_bounds__(256) round_copy2_k(
    const float4* __restrict__ a, float4* __restrict__ ao, int n4a,
    const float4* __restrict__ b, float4* __restrict__ bo, int n4b)
{
    int i = blockIdx.x * 256 + threadIdx.x;
    if (i < n4a) {
        float4 t = a[i];
        t.x = tf32r(t.x); t.y = tf32r(t.y); t.z = tf32r(t.z); t.w = tf32r(t.w);
        ao[i] = t;
    } else if (i < n4a + n4b) {
        int j = i - n4a;
        float4 t = b[j];
        t.x = tf32r(t.x); t.y = tf32r(t.y); t.z = tf32r(t.z); t.w = tf32r(t.w);
        bo[j] = t;
    }
}

__global__ void __launch_bounds__(256) transpose_round4_k(
    const float* __restrict__ W0, float* __restrict__ T0,
    const float* __restrict__ W1, float* __restrict__ T1,
    const float* __restrict__ W2, float* __restrict__ T2,
    const float* __restrict__ W3, float* __restrict__ T3)
{
    const float* W; float* Tt; int K, N;
    switch (blockIdx.z) {
        case 0:  W = W0; Tt = T0; K = QD_;    N = INNER_; break;
        case 1:  W = W1; Tt = T1; K = CD_;    N = INNER_; break;
        case 2:  W = W2; Tt = T2; K = CD_;    N = INNER_; break;
        default: W = W3; Tt = T3; K = INNER_; N = QD_;    break;
    }
    const int n0 = blockIdx.x * 32, k0 = blockIdx.y * 32;
    if (n0 >= N || k0 >= K) return;

    __shared__ float t[32][33];
    const int tx = threadIdx.x & 31, ty = threadIdx.x >> 5;
#pragma unroll
    for (int j = 0; j < 32; j += 8)
        t[ty + j][tx] = W[(long)(k0 + ty + j) * N + n0 + tx];
    __syncthreads();
#pragma unroll
    for (int j = 0; j < 32; j += 8)
        Tt[(long)(n0 + ty + j) * K + k0 + tx] = tf32r(t[tx][ty + j]);
}

// ---------------------------------------------------------------------------
// GEMM core: C tile [128 x 64] at (rt, ct). 4 warps (64x32 each), BK=32,
// 2-stage cp.async, one __syncthreads per chunk. Rows padded to 36 floats.
// Smem: A[128][36] then B[64][36] per stage.
// ---------------------------------------------------------------------------
#define G2STG_F ((128 + 64) * 36)     // 6912 floats per stage
#define G2STG_B (G2STG_F * 4)         // 27648 bytes
#define GEMM_SMEM (2 * G2STG_B)       // 55296 bytes

template <bool BIAS, bool ROUND_OUT>
__device__ __forceinline__ void gemm_core(
    const float* __restrict__ A, const float* __restrict__ Bt,
    float* __restrict__ C, const float* __restrict__ bias,
    int Kd, int ldc, int rt, int ct, float* sm)
{
    const uint32_t sb = smem_u32(sm);
    const int tid  = threadIdx.x;
    const int lane = tid & 31;
    const int w    = tid >> 5;
    const int wm   = w >> 1;      // 0..1 (64-row half)
    const int wn   = w & 1;       // 0..1 (32-col half)
    const int g    = lane >> 2;
    const int tg   = lane & 3;

    // ldmatrix base addrs (relative to stage start)
    const uint32_t aA = ((((wm * 64 + (lane & 15)) * 36) + (lane >> 4) * 4) << 2);
    const uint32_t aB = ((((wn * 32 + ((lane >> 4) << 3) + (lane & 7)) * 36)
                          + ((lane >> 3) & 1) * 4) << 2) + 128 * 36 * 4;

    // staging: A row tid (8 cp16); B row tid>>1, half (tid&1) (4 cp16)
    const float* gA = A + (long)(rt * 128 + tid) * Kd;
    const int br  = tid >> 1;
    const int bc0 = (tid & 1) * 16;
    const float* gB = Bt + (long)(ct * 64 + br) * Kd + bc0;
    const uint32_t stA = sb + ((tid * 36) << 2);
    const uint32_t stB = sb + (((128 + br) * 36 + bc0) << 2);

    float acc[4][4][4];
#pragma unroll
    for (int i = 0; i < 4; i++)
#pragma unroll
        for (int j = 0; j < 4; j++)
#pragma unroll
            for (int t = 0; t < 4; t++) acc[i][j][t] = 0.f;

    const int T = Kd >> 5;

    // prologue: chunk 0 -> stage 0
#pragma unroll
    for (int c = 0; c < 8; c++) cp16(stA + (c << 4), gA + c * 4);
#pragma unroll
    for (int c = 0; c < 4; c++) cp16(stB + (c << 4), gB + c * 4);
    asm volatile("cp.async.commit_group;\n");

    for (int t = 0; t < T; t++) {
        asm volatile("cp.async.wait_group 0;\n");
        __syncthreads();

        if (t + 1 < T) {
            const uint32_t so2 = ((t + 1) & 1) * G2STG_B;
            const int k0 = (t + 1) << 5;
#pragma unroll
            for (int c = 0; c < 8; c++) cp16(stA + so2 + (c << 4), gA + k0 + c * 4);
#pragma unroll
            for (int c = 0; c < 4; c++) cp16(stB + so2 + (c << 4), gB + k0 + c * 4);
            asm volatile("cp.async.commit_group;\n");
        }

        const uint32_t so = (t & 1) * G2STG_B;
#pragma unroll
        for (int kk = 0; kk < 4; kk++) {
            const uint32_t ko = so + kk * 32;
            uint32_t a[4][4], b[4][2];
#pragma unroll
            for (int mi = 0; mi < 4; mi++)
                ldsm4(a[mi][0], a[mi][1], a[mi][2], a[mi][3],
                      sb + aA + ko + mi * (16 * 36 * 4));
#pragma unroll
            for (int p = 0; p < 2; p++)
                ldsm4(b[2 * p][0], b[2 * p][1], b[2 * p + 1][0], b[2 * p + 1][1],
                      sb + aB + ko + p * (16 * 36 * 4));
#pragma unroll
            for (int mi = 0; mi < 4; mi++)
#pragma unroll
                for (int ni = 0; ni < 4; ni++)
                    mma_tf32_u(acc[mi][ni], a[mi], b[ni]);
        }
    }

    // epilogue
#pragma unroll
    for (int mi = 0; mi < 4; mi++) {
        const int r0 = rt * 128 + wm * 64 + mi * 16 + g;
#pragma unroll
        for (int ni = 0; ni < 4; ni++) {
            const int c0 = ct * 64 + wn * 32 + ni * 8 + tg * 2;
            float2 v0 = make_float2(acc[mi][ni][0], acc[mi][ni][1]);
            float2 v1 = make_float2(acc[mi][ni][2], acc[mi][ni][3]);
            if (BIAS) {
                float b0 = __ldg(&bias[c0]), b1 = __ldg(&bias[c0 + 1]);
                v0.x += b0; v0.y += b1; v1.x += b0; v1.y += b1;
            }
            if (ROUND_OUT) {
                v0.x = tf32r(v0.x); v0.y = tf32r(v0.y);
                v1.x = tf32r(v1.x); v1.y = tf32r(v1.y);
            }
            *reinterpret_cast<float2*>(&C[(long)r0 * ldc + c0])       = v0;
            *reinterpret_cast<float2*>(&C[(long)(r0 + 8) * ldc + c0]) = v1;
        }
    }
}

// Fused Q + KV projections in one launch.
// Q: 64 row-tiles x 8 col-tiles = 512; KV: 32 x 16 = 512. Total 1024 CTAs.
__global__ void __launch_bounds__(128, 4) gemm_qkv_k(
    const float* __restrict__ xr, const float* __restrict__ wqt,
    float* __restrict__ q,
    const float* __restrict__ cr, const float* __restrict__ wkvt,
    float* __restrict__ kv)
{
    extern __shared__ float sm[];
    const int bid = blockIdx.x;
    if (bid < 512) {
        gemm_core<false, true>(xr, wqt, q, nullptr, QD_, INNER_,
                               bid >> 3, bid & 7, sm);
    } else {
        const int b2 = bid - 512;
        gemm_core<false, true>(cr, wkvt, kv, nullptr, CD_, KV_LD,
                               b2 >> 4, b2 & 15, sm);
    }
}

// Output projection: 64 row-tiles x 16 col-tiles = 1024 CTAs.
__global__ void __launch_bounds__(128, 4) gemm_out_k(
    const float* __restrict__ o, const float* __restrict__ wot,
    float* __restrict__ out, const float* __restrict__ bout)
{
    extern __shared__ float sm[];
    const int bid = blockIdx.x;
    gemm_core<true, false>(o, wot, out, bout, INNER_, QD_,
                           bid >> 4, bid & 15, sm);
}

// ---------------------------------------------------------------------------
// Fused flash attention (unchanged from round 7): per CTA one (b,h), 128
// q-rows, 16 key-tiles of 64, cp.async double-buffered K/V staging.
// ---------------------------------------------------------------------------
#define FKS  (64 * 68)
#define FVS  (64 * 72)
#define FVB  (2 * FKS)
#define FLASH_SMEM ((2 * FKS + 2 * FVS) * 4)   // 71680 bytes

__global__ void __launch_bounds__(256) flash_attn_k(
    const float* __restrict__ Q, const float* __restrict__ KV,
    float* __restrict__ O)
{
    extern __shared__ float fsm[];
    const uint32_t sb = smem_u32(fsm);

    const int qt = blockIdx.x;
    const int z  = blockIdx.y;
    const int b  = z >> 3, h = z & 7;
    const int tid = threadIdx.x;
    const int wid = tid >> 5;
    const int lane = tid & 31;
    const int g  = lane >> 2;
    const int tg = lane & 3;

    const float* Qb = Q  + (long)b * N_ * INNER_ + h * D_;
    const float* Kb = KV + (long)b * M_ * KV_LD + h * D_;
    const float* Vb = KV + (long)b * M_ * KV_LD + INNER_ + h * D_;

    const int sr = tid >> 4;
    const int sc = (tid & 15) * 4;

#pragma unroll
    for (int jj = 0; jj < 4; jj++) {
        const int r = sr + jj * 16;
        cp16(sb + ((r * 68 + sc) << 2),       Kb + (long)r * KV_LD + sc);
        cp16(sb + ((FVB + r * 72 + sc) << 2), Vb + (long)r * KV_LD + sc);
    }
    asm volatile("cp.async.commit_group;\n");

    float aq[8][4];
    {
        const int r0 = qt * 128 + wid * 16 + g;
#pragma unroll
        for (int kc = 0; kc < 8; kc++) {
            const int c = kc * 8 + tg;
            aq[kc][0] = SCALE_ * __ldg(&Qb[(long)r0 * INNER_ + c]);
            aq[kc][1] = SCALE_ * __ldg(&Qb[(long)(r0 + 8) * INNER_ + c]);
            aq[kc][2] = SCALE_ * __ldg(&Qb[(long)r0 * INNER_ + c + 4]);
            aq[kc][3] = SCALE_ * __ldg(&Qb[(long)(r0 + 8) * INNER_ + c + 4]);
        }
    }

    float m0 = -1e30f, m1 = -1e30f, l0 = 0.f, l1 = 0.f;
    float o[8][4];
#pragma unroll
    for (int ni = 0; ni < 8; ni++)
#pragma unroll
        for (int t = 0; t < 4; t++) o[ni][t] = 0.f;

    for (int jt = 0; jt < 16; jt++) {
        asm volatile("cp.async.wait_group 0;\n");
        __syncthreads();

        if (jt + 1 < 16) {
            const int st = (jt + 1) & 1;
            const int j0 = (jt + 1) * 64;
#pragma unroll
            for (int jj = 0; jj < 4; jj++) {
                const int r = sr + jj * 16;
                cp16(sb + (((st * FKS) + r * 68 + sc) << 2),
                     Kb + (long)(j0 + r) * KV_LD + sc);
                cp16(sb + (((FVB + st * FVS) + r * 72 + sc) << 2),
                     Vb + (long)(j0 + r) * KV_LD + sc);
            }
            asm volatile("cp.async.commit_group;\n");
        }

        const float* Ks = fsm + (jt & 1) * FKS;
        const float* Vs = fsm + FVB + (jt & 1) * FVS;

        float s[8][4];
#pragma unroll
        for (int ni = 0; ni < 8; ni++)
#pragma unroll
            for (int t = 0; t < 4; t++) s[ni][t] = 0.f;
#pragma unroll
        for (int kc = 0; kc < 8; kc++) {
#pragma unroll
            for (int ni = 0; ni < 8; ni++) {
                float bb[2];
                bb[0] = Ks[(ni * 8 + g) * 68 + kc * 8 + tg];
                bb[1] = Ks[(ni * 8 + g) * 68 + kc * 8 + tg + 4];
                mma_tf32(s[ni], aq[kc], bb);
            }
        }

        float rm0 = -1e30f, rm1 = -1e30f;
#pragma unroll
        for (int ni = 0; ni < 8; ni++) {
            rm0 = fmaxf(rm0, fmaxf(s[ni][0], s[ni][1]));
            rm1 = fmaxf(rm1, fmaxf(s[ni][2], s[ni][3]));
        }
#pragma unroll
        for (int off = 1; off <= 2; off <<= 1) {
            rm0 = fmaxf(rm0, __shfl_xor_sync(~0u, rm0, off));
            rm1 = fmaxf(rm1, __shfl_xor_sync(~0u, rm1, off));
        }
        const float mn0 = fmaxf(m0, rm0), mn1 = fmaxf(m1, rm1);
        const float cf0 = __expf(m0 - mn0), cf1 = __expf(m1 - mn1);

        float rs0 = 0.f, rs1 = 0.f;
#pragma unroll
        for (int ni = 0; ni < 8; ni++) {
            s[ni][0] = tf32r(__expf(s[ni][0] - mn0));
            s[ni][1] = tf32r(__expf(s[ni][1] - mn0));
            s[ni][2] = tf32r(__expf(s[ni][2] - mn1));
            s[ni][3] = tf32r(__expf(s[ni][3] - mn1));
            rs0 += s[ni][0] + s[ni][1];
            rs1 += s[ni][2] + s[ni][3];
        }
#pragma unroll
        for (int off = 1; off <= 2; off <<= 1) {
            rs0 += __shfl_xor_sync(~0u, rs0, off);
            rs1 += __shfl_xor_sync(~0u, rs1, off);
        }
        l0 = l0 * cf0 + rs0;
        l1 = l1 * cf1 + rs1;
        m0 = mn0; m1 = mn1;
#pragma unroll
        for (int ni = 0; ni < 8; ni++) {
            o[ni][0] *= cf0; o[ni][1] *= cf0;
            o[ni][2] *= cf1; o[ni][3] *= cf1;
        }

        const int src0 = (lane & 28) | (tg >> 1);
        const int src1 = src0 + 2;
#pragma unroll
        for (int kc = 0; kc < 8; kc++) {
            float x0 = __shfl_sync(~0u, s[kc][0], src0);
            float x1 = __shfl_sync(~0u, s[kc][1], src0);
            float y0 = __shfl_sync(~0u, s[kc][2], src0);
            float y1 = __shfl_sync(~0u, s[kc][3], src0);
            float z0 = __shfl_sync(~0u, s[kc][0], src1);
            float z1 = __shfl_sync(~0u, s[kc][1], src1);
            float u0 = __shfl_sync(~0u, s[kc][2], src1);
            float u1 = __shfl_sync(~0u, s[kc][3], src1);
            float ap[4];
            ap[0] = (tg & 1) ? x1 : x0;
            ap[1] = (tg & 1) ? y1 : y0;
            ap[2] = (tg & 1) ? z1 : z0;
            ap[3] = (tg & 1) ? u1 : u0;
#pragma unroll
            for (int ni = 0; ni < 8; ni++) {
                float bb[2];
                bb[0] = Vs[(kc * 8 + tg) * 72 + ni * 8 + g];
                bb[1] = Vs[(kc * 8 + tg + 4) * 72 + ni * 8 + g];
                mma_tf32(o[ni], ap, bb);
            }
        }
    }

    const float inv0 = 1.0f / l0, inv1 = 1.0f / l1;
    const int r0 = qt * 128 + wid * 16 + g;
    float* Ob = O + (long)b * N_ * INNER_ + h * D_;
#pragma unroll
    for (int ni = 0; ni < 8; ni++) {
        const int c0 = ni * 8 + tg * 2;
        float2 v0 = make_float2(tf32r(o[ni][0] * inv0), tf32r(o[ni][1] * inv0));
        float2 v1 = make_float2(tf32r(o[ni][2] * inv1), tf32r(o[ni][3] * inv1));
        *reinterpret_cast<float2*>(&Ob[(long)r0 * INNER_ + c0])       = v0;
        *reinterpret_cast<float2*>(&Ob[(long)(r0 + 8) * INNER_ + c0]) = v1;
    }
}

// ---------------------------------------------------------------------------
extern "C" void kernel_launch(void* const* d_in, const int* in_sizes, int n_in,
                              void* d_out, int out_size)
{
    const float* x    = (const float*)d_in[0];
    const float* ctx  = (const float*)d_in[1];
    const float* Wq   = (const float*)d_in[2];
    const float* Wk   = (const float*)d_in[3];
    const float* Wv   = (const float*)d_in[4];
    const float* Wout = (const float*)d_in[5];
    const float* bout = (const float*)d_in[6];
    float* out = (float*)d_out;

    float *xr, *cr, *wqt, *wkvt, *wot, *q, *kv, *o;
    cudaGetSymbolAddress((void**)&xr,   g_xr);
    cudaGetSymbolAddress((void**)&cr,   g_cr);
    cudaGetSymbolAddress((void**)&wqt,  g_wqt);
    cudaGetSymbolAddress((void**)&wkvt, g_wkvt);
    cudaGetSymbolAddress((void**)&wot,  g_wot);
    cudaGetSymbolAddress((void**)&q,    g_q);
    cudaGetSymbolAddress((void**)&kv,   g_kv);
    cudaGetSymbolAddress((void**)&o,    g_o);

    cudaFuncSetAttribute(gemm_qkv_k,
                         cudaFuncAttributeMaxDynamicSharedMemorySize, GEMM_SMEM);
    cudaFuncSetAttribute(gemm_out_k,
                         cudaFuncAttributeMaxDynamicSharedMemorySize, GEMM_SMEM);
    cudaFuncSetAttribute(flash_attn_k,
                         cudaFuncAttributeMaxDynamicSharedMemorySize, FLASH_SMEM);

    // ---- prep
    {
        const int n4x = B_ * N_ * QD_ / 4;
        const int n4c = B_ * M_ * CD_ / 4;
        round_copy2_k<<<(n4x + n4c + 255) / 256, 256>>>(
            (const float4*)x, (float4*)xr, n4x,
            (const float4*)ctx, (float4*)cr, n4c);
        transpose_round4_k<<<dim3(32, 32, 4), 256>>>(
            Wq, wqt, Wk, wkvt, Wv, wkvt + (size_t)INNER_ * CD_, Wout, wot);
    }

    // ---- fused Q + K|V projections (1024 CTAs)
    gemm_qkv_k<<<1024, 128, GEMM_SMEM>>>(xr, wqt, q, cr, wkvt, kv);

    // ---- fused attention
    flash_attn_k<<<dim3(16, 32), 256, FLASH_SMEM>>>(q, kv, o);

    // ---- output projection (1024 CTAs)
    gemm_out_k<<<1024, 128, GEMM_SMEM>>>(o, wot, out, bout);
}

// round 9
// speedup vs baseline: 4.8776x; 1.8135x over previous
#include <cuda_runtime.h>
#include <cuda_fp16.h>
#include <cstdint>

// ---------------------------------------------------------------------------
// CrossAttention, full fp16-operand / fp32-accum pipeline (m16n8k16 HMMA).
// b=4, n=2048, m=1024, qd=1024, cd=768, heads=8, dim_head=64, inner=512
// ---------------------------------------------------------------------------

#define B_     4
#define N_     2048
#define M_     1024
#define QD_    1024
#define CD_    768
#define H_     8
#define D_     64
#define INNER_ 512
#define KV_LD  1024
#define SCALE_ 0.125f   // 64^-0.5 (exact power of two)

// Scratch (device globals: allocation-free rule)
__device__ __align__(16) static __half g_xh[(size_t)B_ * N_ * QD_];
__device__ __align__(16) static __half g_ch[(size_t)B_ * M_ * CD_];
__device__ __align__(16) static __half g_wqt[(size_t)INNER_ * QD_];
__device__ __align__(16) static __half g_wkvt[(size_t)KV_LD * CD_];   // [Wk^T; Wv^T]
__device__ __align__(16) static __half g_wot[(size_t)QD_ * INNER_];
__device__ __align__(16) static __half g_q[(size_t)B_ * N_ * INNER_];
__device__ __align__(16) static __half g_kv[(size_t)B_ * M_ * KV_LD]; // K | V
__device__ __align__(16) static __half g_o[(size_t)B_ * N_ * INNER_];

__device__ __forceinline__ uint32_t smem_u32(const void* p) {
    return (uint32_t)__cvta_generic_to_shared(p);
}
__device__ __forceinline__ void cp16(uint32_t saddr, const void* g) {
    asm volatile("cp.async.cg.shared.global [%0], [%1], 16;\n" :: "r"(saddr), "l"(g));
}
__device__ __forceinline__ void ldsm4(uint32_t& r0, uint32_t& r1, uint32_t& r2,
                                      uint32_t& r3, uint32_t addr) {
    asm volatile("ldmatrix.sync.aligned.m8n8.x4.shared.b16 {%0,%1,%2,%3}, [%4];"
                 : "=r"(r0), "=r"(r1), "=r"(r2), "=r"(r3) : "r"(addr));
}
__device__ __forceinline__ void ldsm4t(uint32_t& r0, uint32_t& r1, uint32_t& r2,
                                       uint32_t& r3, uint32_t addr) {
    asm volatile("ldmatrix.sync.aligned.m8n8.x4.trans.shared.b16 {%0,%1,%2,%3}, [%4];"
                 : "=r"(r0), "=r"(r1), "=r"(r2), "=r"(r3) : "r"(addr));
}
__device__ __forceinline__ void mma_f16(float c[4], const uint32_t a[4],
                                        const uint32_t b[2]) {
    asm volatile(
        "mma.sync.aligned.m16n8k16.row.col.f32.f16.f16.f32 "
        "{%0,%1,%2,%3}, {%4,%5,%6,%7}, {%8,%9}, {%0,%1,%2,%3};\n"
        : "+f"(c[0]), "+f"(c[1]), "+f"(c[2]), "+f"(c[3])
        : "r"(a[0]), "r"(a[1]), "r"(a[2]), "r"(a[3]), "r"(b[0]), "r"(b[1]));
}
__device__ __forceinline__ uint32_t packh2(float lo, float hi) {
    __half2 h = __floats2half2_rn(lo, hi);
    return *reinterpret_cast<uint32_t*>(&h);
}

// ---------------------------------------------------------------------------
// Prep: fp16-round copies (x, ctx) and 4-way transpose+round (weights).
// ---------------------------------------------------------------------------
__global__ void __launch_bounds__(256) round_copy2h_k(
    const float4* __restrict__ a, uint2* __restrict__ ao, int n4a,
    const float4* __restrict__ b, uint2* __restrict__ bo, int n4b)
{
    int i = blockIdx.x * 256 + threadIdx.x;
    if (i < n4a) {
        float4 t = a[i];
        uint2 r; r.x = packh2(t.x, t.y); r.y = packh2(t.z, t.w);
        ao[i] = r;
    } else if (i < n4a + n4b) {
        int j = i - n4a;
        float4 t = b[j];
        uint2 r; r.x = packh2(t.x, t.y); r.y = packh2(t.z, t.w);
        bo[j] = r;
    }
}

__global__ void __launch_bounds__(256) transpose_round4h_k(
    const float* __restrict__ W0, __half* __restrict__ T0,
    const float* __restrict__ W1, __half* __restrict__ T1,
    const float* __restrict__ W2, __half* __restrict__ T2,
    const float* __restrict__ W3, __half* __restrict__ T3)
{
    const float* W; __half* Tt; int K, N;
    switch (blockIdx.z) {
        case 0:  W = W0; Tt = T0; K = QD_;    N = INNER_; break;
        case 1:  W = W1; Tt = T1; K = CD_;    N = INNER_; break;
        case 2:  W = W2; Tt = T2; K = CD_;    N = INNER_; break;
        default: W = W3; Tt = T3; K = INNER_; N = QD_;    break;
    }
    const int n0 = blockIdx.x * 32, k0 = blockIdx.y * 32;
    if (n0 >= N || k0 >= K) return;

    __shared__ float t[32][33];
    const int tx = threadIdx.x & 31, ty = threadIdx.x >> 5;
#pragma unroll
    for (int j = 0; j < 32; j += 8)
        t[ty + j][tx] = W[(long)(k0 + ty + j) * N + n0 + tx];
    __syncthreads();
#pragma unroll
    for (int j = 0; j < 32; j += 8)
        Tt[(long)(n0 + ty + j) * K + k0 + tx] = __float2half_rn(t[tx][ty + j]);
}

// ---------------------------------------------------------------------------
// fp16 GEMM core: C[128x128 tile] = A[M][K] * Bt[N][K]^T.
// 4 warps (64x64 each), BK=64 halfs (128B rows), 2-stage cp.async,
// one __syncthreads per chunk, ldmatrix b16. Rows padded to 72 halfs (144B)
// -> conflict-free LDSM (granule 9r mod 8 = r) and 16B-aligned rows.
// ---------------------------------------------------------------------------
#define LDKH    72
#define HSTG_B  ((128 + 128) * LDKH * 2)   // 36864 B per stage
#define GEMM_SMEM (2 * HSTG_B)             // 73728 B

template <bool OUT_HALF, bool BIAS>
__device__ __forceinline__ void gemm_core_h(
    const __half* __restrict__ A, const __half* __restrict__ Bt,
    void* __restrict__ Cv, const float* __restrict__ bias,
    int Kd, int ldc, int rt, int ct, char* sm)
{
    const uint32_t sb = smem_u32(sm);
    const int tid  = threadIdx.x;
    const int lane = tid & 31;
    const int w    = tid >> 5;
    const int wm   = w >> 1;
    const int wn   = w & 1;
    const int g    = lane >> 2;
    const int tg   = lane & 3;

    // ldmatrix bases (stage-relative): row (lane&15), k-half (lane>>4)*8
    const uint32_t aA = sb + ((((wm * 64 + (lane & 15)) * LDKH)
                               + ((lane >> 4) << 3)) << 1);
    const uint32_t aB = sb + (128 * LDKH * 2)
                        + ((((wn * 64 + (lane & 15)) * LDKH)
                            + ((lane >> 4) << 3)) << 1);

    // staging: thread -> A row tid, B row tid; 8 cp16 each (128B)
    const __half* gA = A  + (size_t)(rt * 128 + tid) * Kd;
    const __half* gB = Bt + (size_t)(ct * 128 + tid) * Kd;
    const uint32_t stA = sb + ((tid * LDKH) << 1);
    const uint32_t stB = sb + (128 * LDKH * 2) + ((tid * LDKH) << 1);

    float acc[4][8][4];
#pragma unroll
    for (int i = 0; i < 4; i++)
#pragma unroll
        for (int j = 0; j < 8; j++)
#pragma unroll
            for (int t = 0; t < 4; t++) acc[i][j][t] = 0.f;

    const int T = Kd >> 6;   // chunks of 64 halfs

#pragma unroll
    for (int c = 0; c < 8; c++) {
        cp16(stA + (c << 4), gA + c * 8);
        cp16(stB + (c << 4), gB + c * 8);
    }
    asm volatile("cp.async.commit_group;\n");

    for (int t = 0; t < T; t++) {
        asm volatile("cp.async.wait_group 0;\n");
        __syncthreads();

        if (t + 1 < T) {
            const uint32_t so2 = ((t + 1) & 1) * HSTG_B;
            const int k0 = (t + 1) << 6;
#pragma unroll
            for (int c = 0; c < 8; c++) {
                cp16(stA + so2 + (c << 4), gA + k0 + c * 8);
                cp16(stB + so2 + (c << 4), gB + k0 + c * 8);
            }
            asm volatile("cp.async.commit_group;\n");
        }

        const uint32_t so = (t & 1) * HSTG_B;
#pragma unroll
        for (int kk = 0; kk < 4; kk++) {
            const uint32_t ko = so + kk * 32;   // 16 halfs
            uint32_t a[4][4], b[8][2];
#pragma unroll
            for (int mi = 0; mi < 4; mi++)
                ldsm4(a[mi][0], a[mi][1], a[mi][2], a[mi][3],
                      aA + ko + mi * (16 * LDKH * 2));
#pragma unroll
            for (int p = 0; p < 4; p++) {
                uint32_t r0, r1, r2, r3;
                ldsm4(r0, r1, r2, r3, aB + ko + p * (16 * LDKH * 2));
                b[2 * p][0] = r0; b[2 * p][1] = r2;
                b[2 * p + 1][0] = r1; b[2 * p + 1][1] = r3;
            }
#pragma unroll
            for (int mi = 0; mi < 4; mi++)
#pragma unroll
                for (int ni = 0; ni < 8; ni++)
                    mma_f16(acc[mi][ni], a[mi], b[ni]);
        }
    }

    // epilogue
#pragma unroll
    for (int mi = 0; mi < 4; mi++) {
        const int r0 = rt * 128 + wm * 64 + mi * 16 + g;
#pragma unroll
        for (int ni = 0; ni < 8; ni++) {
            const int c0 = ct * 128 + wn * 64 + ni * 8 + tg * 2;
            if (OUT_HALF) {
                __half* C = (__half*)Cv;
                __half2 v0 = __floats2half2_rn(acc[mi][ni][0], acc[mi][ni][1]);
                __half2 v1 = __floats2half2_rn(acc[mi][ni][2], acc[mi][ni][3]);
                *reinterpret_cast<__half2*>(&C[(size_t)r0 * ldc + c0])       = v0;
                *reinterpret_cast<__half2*>(&C[(size_t)(r0 + 8) * ldc + c0]) = v1;
            } else {
                float* C = (float*)Cv;
                float2 v0 = make_float2(acc[mi][ni][0], acc[mi][ni][1]);
                float2 v1 = make_float2(acc[mi][ni][2], acc[mi][ni][3]);
                if (BIAS) {
                    float b0 = __ldg(&bias[c0]), b1 = __ldg(&bias[c0 + 1]);
                    v0.x += b0; v0.y += b1; v1.x += b0; v1.y += b1;
                }
                *reinterpret_cast<float2*>(&C[(size_t)r0 * ldc + c0])       = v0;
                *reinterpret_cast<float2*>(&C[(size_t)(r0 + 8) * ldc + c0]) = v1;
            }
        }
    }
}

// Fused Q + KV projections: Q 64x4=256 tiles, KV 32x8=256 tiles -> 512 CTAs.
__global__ void __launch_bounds__(128) gemm_qkv_k(
    const __half* __restrict__ xh, const __half* __restrict__ wqt,
    __half* __restrict__ q,
    const __half* __restrict__ ch, const __half* __restrict__ wkvt,
    __half* __restrict__ kv)
{
    extern __shared__ char smc[];
    const int bid = blockIdx.x;
    if (bid < 256) {
        gemm_core_h<true, false>(xh, wqt, q, nullptr, QD_, INNER_,
                                 bid >> 2, bid & 3, smc);
    } else {
        const int b2 = bid - 256;
        gemm_core_h<true, false>(ch, wkvt, kv, nullptr, CD_, KV_LD,
                                 b2 >> 3, b2 & 7, smc);
    }
}

// Output projection: 64 x 8 = 512 CTAs.
__global__ void __launch_bounds__(128) gemm_out_k(
    const __half* __restrict__ o, const __half* __restrict__ wot,
    float* __restrict__ out, const float* __restrict__ bout)
{
    extern __shared__ char smc[];
    const int bid = blockIdx.x;
    gemm_core_h<false, true>(o, wot, out, bout, INNER_, QD_,
                             bid >> 3, bid & 7, smc);
}

// ---------------------------------------------------------------------------
// Fused fp16 flash attention: per CTA one (b,h), 128 q-rows, 16 key-tiles
// of 64. 8 warps x 16 q-rows. Q frags in regs (ldmatrix once, scale folded).
// K frags via ldmatrix, V frags via ldmatrix.trans, P reused as A-frags
// directly from C-frag layout (fp16 identity) -- no shuffles, no P smem.
// Smem: Q[128][72]h, then K stages 2x[64][72]h, V stages 2x[64][72]h.
// ---------------------------------------------------------------------------
#define FQ_B   (128 * LDKH * 2)          // 18432
#define FT_B   (64 * LDKH * 2)           // 9216 per K/V stage
#define FLASH_SMEM (FQ_B + 4 * FT_B)     // 55296

__global__ void __launch_bounds__(256) flash_attn_h(
    const __half* __restrict__ Q, const __half* __restrict__ KV,
    __half* __restrict__ O)
{
    extern __shared__ char smc[];
    const uint32_t sb = smem_u32(smc);

    const int qt = blockIdx.x;
    const int z  = blockIdx.y;
    const int b  = z >> 3, h = z & 7;
    const int tid = threadIdx.x;
    const int wid = tid >> 5;
    const int lane = tid & 31;
    const int g  = lane >> 2;
    const int tg = lane & 3;

    const __half* Qb = Q  + (size_t)b * N_ * INNER_ + h * D_;
    const __half* Kb = KV + (size_t)b * M_ * KV_LD + h * D_;
    const __half* Vb = KV + (size_t)b * M_ * KV_LD + INNER_ + h * D_;

    // ---- prologue staging: Q tile (16KB) + K/V tile 0
    {
        const int qr = tid >> 1, qc = (tid & 1) * 32;   // halfs
#pragma unroll
        for (int i = 0; i < 4; i++)
            cp16(sb + (((qr * LDKH + qc) << 1) + (i << 4)),
                 Qb + (size_t)(qt * 128 + qr) * INNER_ + qc + i * 8);
        const int kr = tid >> 2, kc = (tid & 3) * 16;
#pragma unroll
        for (int i = 0; i < 2; i++) {
            cp16(sb + FQ_B + (((kr * LDKH + kc) << 1) + (i << 4)),
                 Kb + (size_t)kr * KV_LD + kc + i * 8);
            cp16(sb + FQ_B + 2 * FT_B + (((kr * LDKH + kc) << 1) + (i << 4)),
                 Vb + (size_t)kr * KV_LD + kc + i * 8);
        }
        asm volatile("cp.async.commit_group;\n");
    }
    asm volatile("cp.async.wait_group 0;\n");
    __syncthreads();

    // ---- Q fragments (ldmatrix), fold in softmax scale (exact pow2)
    uint32_t aq[4][4];
    {
        const uint32_t qbase = sb + ((((wid * 16 + (lane & 15)) * LDKH)
                                      + ((lane >> 4) << 3)) << 1);
#pragma unroll
        for (int kc = 0; kc < 4; kc++)
            ldsm4(aq[kc][0], aq[kc][1], aq[kc][2], aq[kc][3], qbase + kc * 32);
        const __half2 sc = __float2half2_rn(SCALE_);
#pragma unroll
        for (int kc = 0; kc < 4; kc++)
#pragma unroll
            for (int i = 0; i < 4; i++) {
                __half2 v = *reinterpret_cast<__half2*>(&aq[kc][i]);
                v = __hmul2(v, sc);
                aq[kc][i] = *reinterpret_cast<uint32_t*>(&v);
            }
    }

    float m0 = -1e30f, m1 = -1e30f, l0 = 0.f, l1 = 0.f;
    float o[8][4];
#pragma unroll
    for (int ni = 0; ni < 8; ni++)
#pragma unroll
        for (int t = 0; t < 4; t++) o[ni][t] = 0.f;

    const int sr15 = lane & 15;
    const int sk8  = (lane >> 4) << 3;

    for (int jt = 0; jt < 16; jt++) {
        // prefetch next tile into other stage
        if (jt + 1 < 16) {
            const int st = (jt + 1) & 1;
            const int j0 = (jt + 1) * 64;
            const int kr = tid >> 2, kc = (tid & 3) * 16;
#pragma unroll
            for (int i = 0; i < 2; i++) {
                cp16(sb + FQ_B + st * FT_B + (((kr * LDKH + kc) << 1) + (i << 4)),
                     Kb + (size_t)(j0 + kr) * KV_LD + kc + i * 8);
                cp16(sb + FQ_B + 2 * FT_B + st * FT_B
                        + (((kr * LDKH + kc) << 1) + (i << 4)),
                     Vb + (size_t)(j0 + kr) * KV_LD + kc + i * 8);
            }
            asm volatile("cp.async.commit_group;\n");
        }

        const uint32_t ksb = sb + FQ_B + (jt & 1) * FT_B;
        const uint32_t vsb = sb + FQ_B + 2 * FT_B + (jt & 1) * FT_B;

        // ---- S = (scaled Q) K^T : 32 k16-MMAs per warp
        float s[8][4];
#pragma unroll
        for (int ni = 0; ni < 8; ni++)
#pragma unroll
            for (int t = 0; t < 4; t++) s[ni][t] = 0.f;
#pragma unroll
        for (int kc = 0; kc < 4; kc++) {
            uint32_t bk[8][2];
#pragma unroll
            for (int p = 0; p < 4; p++) {
                uint32_t r0, r1, r2, r3;
                ldsm4(r0, r1, r2, r3,
                      ksb + ((((p * 16 + sr15) * LDKH) + kc * 16 + sk8) << 1));
                bk[2 * p][0] = r0; bk[2 * p][1] = r2;
                bk[2 * p + 1][0] = r1; bk[2 * p + 1][1] = r3;
            }
#pragma unroll
            for (int ni = 0; ni < 8; ni++)
                mma_f16(s[ni], aq[kc], bk[ni]);
        }

        // ---- online softmax (rows g, g+8)
        float rm0 = -1e30f, rm1 = -1e30f;
#pragma unroll
        for (int ni = 0; ni < 8; ni++) {
            rm0 = fmaxf(rm0, fmaxf(s[ni][0], s[ni][1]));
            rm1 = fmaxf(rm1, fmaxf(s[ni][2], s[ni][3]));
        }
#pragma unroll
        for (int off = 1; off <= 2; off <<= 1) {
            rm0 = fmaxf(rm0, __shfl_xor_sync(~0u, rm0, off));
            rm1 = fmaxf(rm1, __shfl_xor_sync(~0u, rm1, off));
        }
        const float mn0 = fmaxf(m0, rm0), mn1 = fmaxf(m1, rm1);
        const float cf0 = __expf(m0 - mn0), cf1 = __expf(m1 - mn1);

        float rs0 = 0.f, rs1 = 0.f;
#pragma unroll
        for (int ni = 0; ni < 8; ni++) {
            s[ni][0] = __expf(s[ni][0] - mn0);
            s[ni][1] = __expf(s[ni][1] - mn0);
            s[ni][2] = __expf(s[ni][2] - mn1);
            s[ni][3] = __expf(s[ni][3] - mn1);
            rs0 += s[ni][0] + s[ni][1];
            rs1 += s[ni][2] + s[ni][3];
        }
#pragma unroll
        for (int off = 1; off <= 2; off <<= 1) {
            rs0 += __shfl_xor_sync(~0u, rs0, off);
            rs1 += __shfl_xor_sync(~0u, rs1, off);
        }
        l0 = l0 * cf0 + rs0;
        l1 = l1 * cf1 + rs1;
        m0 = mn0; m1 = mn1;
#pragma unroll
        for (int ni = 0; ni < 8; ni++) {
            o[ni][0] *= cf0; o[ni][1] *= cf0;
            o[ni][2] *= cf1; o[ni][3] *= cf1;
        }

        // ---- O += P V : P C-frags reused as A-frags directly (fp16 identity)
#pragma unroll
        for (int j = 0; j < 4; j++) {
            uint32_t ap[4];
            ap[0] = packh2(s[2 * j][0],     s[2 * j][1]);
            ap[1] = packh2(s[2 * j][2],     s[2 * j][3]);
            ap[2] = packh2(s[2 * j + 1][0], s[2 * j + 1][1]);
            ap[3] = packh2(s[2 * j + 1][2], s[2 * j + 1][3]);
            uint32_t bv[8][2];
#pragma unroll
            for (int p = 0; p < 4; p++) {
                uint32_t r0, r1, r2, r3;
                ldsm4t(r0, r1, r2, r3,
                       vsb + ((((j * 16 + sr15) * LDKH) + p * 16 + sk8) << 1));
                bv[2 * p][0] = r0; bv[2 * p][1] = r1;
                bv[2 * p + 1][0] = r2; bv[2 * p + 1][1] = r3;
            }
#pragma unroll
            for (int ni = 0; ni < 8; ni++)
                mma_f16(o[ni], ap, bv[ni]);
        }

        if (jt + 1 < 16) {
            asm volatile("cp.async.wait_group 0;\n");
            __syncthreads();
        }
    }

    // ---- epilogue: normalize, store half
    const float inv0 = 1.0f / l0, inv1 = 1.0f / l1;
    const int r0 = qt * 128 + wid * 16 + g;
    __half* Ob = O + (size_t)b * N_ * INNER_ + h * D_;
#pragma unroll
    for (int ni = 0; ni < 8; ni++) {
        const int c0 = ni * 8 + tg * 2;
        __half2 v0 = __floats2half2_rn(o[ni][0] * inv0, o[ni][1] * inv0);
        __half2 v1 = __floats2half2_rn(o[ni][2] * inv1, o[ni][3] * inv1);
        *reinterpret_cast<__half2*>(&Ob[(size_t)r0 * INNER_ + c0])       = v0;
        *reinterpret_cast<__half2*>(&Ob[(size_t)(r0 + 8) * INNER_ + c0]) = v1;
    }
}

// ---------------------------------------------------------------------------
extern "C" void kernel_launch(void* const* d_in, const int* in_sizes, int n_in,
                              void* d_out, int out_size)
{
    const float* x    = (const float*)d_in[0];
    const float* ctx  = (const float*)d_in[1];
    const float* Wq   = (const float*)d_in[2];
    const float* Wk   = (const float*)d_in[3];
    const float* Wv   = (const float*)d_in[4];
    const float* Wout = (const float*)d_in[5];
    const float* bout = (const float*)d_in[6];
    float* out = (float*)d_out;

    __half *xh, *ch, *wqt, *wkvt, *wot, *q, *kv, *o;
    cudaGetSymbolAddress((void**)&xh,   g_xh);
    cudaGetSymbolAddress((void**)&ch,   g_ch);
    cudaGetSymbolAddress((void**)&wqt,  g_wqt);
    cudaGetSymbolAddress((void**)&wkvt, g_wkvt);
    cudaGetSymbolAddress((void**)&wot,  g_wot);
    cudaGetSymbolAddress((void**)&q,    g_q);
    cudaGetSymbolAddress((void**)&kv,   g_kv);
    cudaGetSymbolAddress((void**)&o,    g_o);

    cudaFuncSetAttribute(gemm_qkv_k,
                         cudaFuncAttributeMaxDynamicSharedMemorySize, GEMM_SMEM);
    cudaFuncSetAttribute(gemm_out_k,
                         cudaFuncAttributeMaxDynamicSharedMemorySize, GEMM_SMEM);
    cudaFuncSetAttribute(flash_attn_h,
                         cudaFuncAttributeMaxDynamicSharedMemorySize, FLASH_SMEM);

    // ---- prep
    {
        const int n4x = B_ * N_ * QD_ / 4;
        const int n4c = B_ * M_ * CD_ / 4;
        round_copy2h_k<<<(n4x + n4c + 255) / 256, 256>>>(
            (const float4*)x, (uint2*)xh, n4x,
            (const float4*)ctx, (uint2*)ch, n4c);
        transpose_round4h_k<<<dim3(32, 32, 4), 256>>>(
            Wq, wqt, Wk, wkvt, Wv, wkvt + (size_t)INNER_ * CD_, Wout, wot);
    }

    // ---- fused Q + K|V projections (512 CTAs)
    gemm_qkv_k<<<512, 128, GEMM_SMEM>>>(xh, wqt, q, ch, wkvt, kv);

    // ---- fused attention
    flash_attn_h<<<dim3(16, 32), 256, FLASH_SMEM>>>(q, kv, o);

    // ---- output projection (+bias)
    gemm_out_k<<<512, 128, GEMM_SMEM>>>(o, wot, out, bout);
}